// round 13
// baseline (speedup 1.0000x reference)
#include <cuda_runtime.h>
#include <cuda_bf16.h>
#include <math.h>
#include <stdint.h>

// ---------------- problem constants (fixed shapes) ----------------
#define B_  2
#define S_  2048
#define D_  1024
#define H_  16
#define KS  16      // splats per head
#define HD  64      // head dim
#define TD  (3*D_)  // qkv row width = 3072
#define IR  8       // influence radius
#define KDIM 1024   // GEMM K for both projections

typedef unsigned long long u64;

// ---------------- packed f32x2 helpers ----------------
__device__ __forceinline__ float2 up2(u64 v) {
    float2 r; asm("mov.b64 {%0, %1}, %2;" : "=f"(r.x), "=f"(r.y) : "l"(v)); return r;
}
__device__ __forceinline__ u64 ffma2(u64 a, u64 b, u64 c) {
    u64 d; asm("fma.rn.f32x2 %0, %1, %2, %3;" : "=l"(d) : "l"(a), "l"(b), "l"(c));
    return d;
}

// ---------------- warp MMA helpers (sm_80 baseline PTX) ----
__device__ __forceinline__ uint32_t smem_u32(const void* p) {
    uint32_t a;
    asm("{ .reg .u64 t; cvta.to.shared.u64 t, %1; cvt.u32.u64 %0, t; }" : "=r"(a) : "l"(p));
    return a;
}
__device__ __forceinline__ void ldsm4(uint32_t addr, uint32_t* r) {
    asm volatile("ldmatrix.sync.aligned.m8n8.x4.shared.b16 {%0,%1,%2,%3}, [%4];"
                 : "=r"(r[0]), "=r"(r[1]), "=r"(r[2]), "=r"(r[3]) : "r"(addr));
}
__device__ __forceinline__ void ldsm4t(uint32_t addr, uint32_t* r) {
    asm volatile("ldmatrix.sync.aligned.m8n8.x4.trans.shared.b16 {%0,%1,%2,%3}, [%4];"
                 : "=r"(r[0]), "=r"(r[1]), "=r"(r[2]), "=r"(r[3]) : "r"(addr));
}
__device__ __forceinline__ void mma_bf16(float* c, const uint32_t* a, const uint32_t* b) {
    asm volatile("mma.sync.aligned.m16n8k16.row.col.f32.bf16.bf16.f32 "
                 "{%0,%1,%2,%3}, {%4,%5,%6,%7}, {%8,%9}, {%0,%1,%2,%3};"
                 : "+f"(c[0]), "+f"(c[1]), "+f"(c[2]), "+f"(c[3])
                 : "r"(a[0]), "r"(a[1]), "r"(a[2]), "r"(a[3]), "r"(b[0]), "r"(b[1]));
}
__device__ __forceinline__ uint32_t cvt2bf(float lo, float hi) {
    uint32_t r; asm("cvt.rn.bf16x2.f32 %0, %1, %2;" : "=r"(r) : "f"(hi), "f"(lo)); return r;
}
__device__ __forceinline__ float bflo(uint32_t p) { return __uint_as_float(p << 16); }
__device__ __forceinline__ float bfhi(uint32_t p) { return __uint_as_float(p & 0xffff0000u); }

// ---------------- scratch (device globals; no allocation allowed) ----------------
// NOTE: reference these ONLY from device code (host-shadow pitfall, R6/R7).
__device__ __align__(16) float g_qkv[(size_t)B_ * S_ * TD];
__device__ float g_mw [B_ * (S_-1)];
__device__ float g_im [B_ * (S_-1)];
__device__ __align__(16) __nv_bfloat16 g_xh [(size_t)B_ * S_ * D_];
__device__ __align__(16) __nv_bfloat16 g_xl [(size_t)B_ * S_ * D_];
__device__ __align__(16) __nv_bfloat16 g_wh [(size_t)TD * D_];
__device__ __align__(16) __nv_bfloat16 g_wl [(size_t)TD * D_];
__device__ __align__(16) __nv_bfloat16 g_aoh[(size_t)B_ * S_ * D_];
__device__ __align__(16) __nv_bfloat16 g_aol[(size_t)B_ * S_ * D_];
__device__ __align__(16) __nv_bfloat16 g_owh[(size_t)D_ * D_];
__device__ __align__(16) __nv_bfloat16 g_owl[(size_t)D_ * D_];
__device__ __align__(16) __nv_bfloat16 g_qwh[(size_t)B_ * H_ * S_ * KS];
__device__ __align__(16) __nv_bfloat16 g_qwl[(size_t)B_ * H_ * S_ * KS];
__device__ __align__(16) __nv_bfloat16 g_kwh[(size_t)B_ * H_ * S_ * KS];
__device__ __align__(16) __nv_bfloat16 g_kwl[(size_t)B_ * H_ * S_ * KS];
__device__ __align__(16) __nv_bfloat16 g_vh [(size_t)B_ * S_ * D_];
__device__ __align__(16) __nv_bfloat16 g_vl [(size_t)B_ * S_ * D_];

// ======================================================================
// fp32 -> (hi, lo) bf16 split
// ======================================================================
__device__ __forceinline__ void split_body(const float* __restrict__ in,
                                           __nv_bfloat16* __restrict__ hi,
                                           __nv_bfloat16* __restrict__ lo, int n4)
{
    int i = blockIdx.x * blockDim.x + threadIdx.x;
    if (i >= n4) return;
    float4 v = ((const float4*)in)[i];
    float f[4] = {v.x, v.y, v.z, v.w};
    unsigned short hb[4], lb[4];
    #pragma unroll
    for (int j = 0; j < 4; ++j) {
        __nv_bfloat16 h = __float2bfloat16(f[j]);
        float hf = __bfloat162float(h);
        __nv_bfloat16 l = __float2bfloat16(f[j] - hf);
        hb[j] = __bfloat16_as_ushort(h);
        lb[j] = __bfloat16_as_ushort(l);
    }
    ((ushort4*)hi)[i] = make_ushort4(hb[0], hb[1], hb[2], hb[3]);
    ((ushort4*)lo)[i] = make_ushort4(lb[0], lb[1], lb[2], lb[3]);
}

__global__ __launch_bounds__(256)
void split_x_kernel(const float* __restrict__ in)
{ split_body(in, g_xh, g_xl, (B_ * S_ * D_) / 4); }

__global__ __launch_bounds__(256)
void split_w_kernel(const float* __restrict__ in)
{ split_body(in, g_wh, g_wl, (TD * D_) / 4); }

__global__ __launch_bounds__(256)
void split_ow_kernel(const float* __restrict__ in)
{ split_body(in, g_owh, g_owl, (D_ * D_) / 4); }

// ======================================================================
// HMMA split-bf16 GEMM: C[M,N] = A[M,K]*B[N,K]^T, fp32 out.
// Single-stage register-prefetch (R9-proven, fastest measured).
// WV=true (QKV gemm): tiles with n0>=2D are V -> bf16 hi/lo direct.
// ======================================================================
#define RSB   80
#define ARR_B (128 * RSB)
#define SS_SMEM_BYTES (4 * ARR_B)   // 40960 B

template<bool WV>
__device__ __forceinline__ void hmma_gemm_body(
    const __nv_bfloat16* __restrict__ Ah, const __nv_bfloat16* __restrict__ Al,
    const __nv_bfloat16* __restrict__ Bh, const __nv_bfloat16* __restrict__ Bl,
    float* __restrict__ C, int N)
{
    extern __shared__ char smem_raw[];
    const uint32_t base = smem_u32(smem_raw);

    const int tid  = threadIdx.x;
    const int lane = tid & 31;
    const int warp = tid >> 5;
    const int wm = warp >> 2;
    const int wn = warp & 3;
    const int m0 = blockIdx.y * 128;
    const int n0 = blockIdx.x * 128;

    const int j   = lane >> 3;
    const int rin = lane & 7;
    const uint32_t a_row = wm * 64 + ((j & 1) << 3) + rin;
    const uint32_t a_kb  = (j >> 1) << 4;
    const uint32_t b_row = wn * 32 + ((j >> 1) << 3) + rin;
    const uint32_t b_kb  = (j & 1) << 4;

    const int g_row0 = tid >> 2;
    const int g_cg   = tid & 3;

    float acc[4][4][4];
    #pragma unroll
    for (int mi = 0; mi < 4; ++mi)
        #pragma unroll
        for (int ni = 0; ni < 4; ++ni)
            #pragma unroll
            for (int q = 0; q < 4; ++q) acc[mi][ni][q] = 0.f;

    const __nv_bfloat16* srcs[4] = { Ah, Al, Bh, Bl };

    #pragma unroll
    for (int arr = 0; arr < 4; ++arr) {
        const __nv_bfloat16* src = srcs[arr];
        const int rbase = (arr < 2) ? m0 : n0;
        #pragma unroll
        for (int i = 0; i < 2; ++i) {
            int row = g_row0 + i * 64;
            uint4 v = *(const uint4*)(src + (size_t)(rbase + row) * KDIM + g_cg * 8);
            uint32_t sa = base + arr * ARR_B + row * RSB + g_cg * 16;
            asm volatile("st.shared.v4.b32 [%0], {%1,%2,%3,%4};"
                         :: "r"(sa), "r"(v.x), "r"(v.y), "r"(v.z), "r"(v.w) : "memory");
        }
    }
    __syncthreads();

    const int CH = KDIM / 32;
    for (int c = 0; c < CH; ++c) {
        uint4 pre[4][2];
        const bool more = (c + 1 < CH);
        if (more) {
            #pragma unroll
            for (int arr = 0; arr < 4; ++arr) {
                const __nv_bfloat16* src = srcs[arr];
                const int rbase = (arr < 2) ? m0 : n0;
                #pragma unroll
                for (int i = 0; i < 2; ++i) {
                    int row = g_row0 + i * 64;
                    pre[arr][i] = *(const uint4*)(src + (size_t)(rbase + row) * KDIM + (c + 1) * 32 + g_cg * 8);
                }
            }
        }

        #pragma unroll
        for (int ks = 0; ks < 2; ++ks) {
            const uint32_t kbo = ks * 32;
            uint32_t ah[4][4], al[4][4], bh[4][2], bl[4][2];
            #pragma unroll
            for (int mi = 0; mi < 4; ++mi) {
                uint32_t addr = base + (a_row + mi * 16) * RSB + kbo + a_kb;
                ldsm4(addr, ah[mi]);
                ldsm4(addr + ARR_B, al[mi]);
            }
            #pragma unroll
            for (int p = 0; p < 2; ++p) {
                uint32_t addr = base + 2 * ARR_B + (b_row + p * 16) * RSB + kbo + b_kb;
                uint32_t rh[4], rl[4];
                ldsm4(addr, rh);
                ldsm4(addr + ARR_B, rl);
                bh[p*2+0][0] = rh[0]; bh[p*2+0][1] = rh[1];
                bh[p*2+1][0] = rh[2]; bh[p*2+1][1] = rh[3];
                bl[p*2+0][0] = rl[0]; bl[p*2+0][1] = rl[1];
                bl[p*2+1][0] = rl[2]; bl[p*2+1][1] = rl[3];
            }
            #pragma unroll
            for (int mi = 0; mi < 4; ++mi)
                #pragma unroll
                for (int ni = 0; ni < 4; ++ni) {
                    mma_bf16(acc[mi][ni], ah[mi], bh[ni]);
                    mma_bf16(acc[mi][ni], al[mi], bh[ni]);
                    mma_bf16(acc[mi][ni], ah[mi], bl[ni]);
                }
        }
        __syncthreads();

        if (more) {
            #pragma unroll
            for (int arr = 0; arr < 4; ++arr)
                #pragma unroll
                for (int i = 0; i < 2; ++i) {
                    int row = g_row0 + i * 64;
                    uint32_t sa = base + arr * ARR_B + row * RSB + g_cg * 16;
                    uint4 v = pre[arr][i];
                    asm volatile("st.shared.v4.b32 [%0], {%1,%2,%3,%4};"
                                 :: "r"(sa), "r"(v.x), "r"(v.y), "r"(v.z), "r"(v.w) : "memory");
                }
            __syncthreads();
        }
    }

    const int qr = lane >> 2;
    const int qc = (lane & 3) * 2;
    if (WV && n0 >= 2 * D_) {
        // V tile: write bf16 hi/lo splits directly (replaces split_v)
        const int cb = n0 - 2 * D_;
        #pragma unroll
        for (int mi = 0; mi < 4; ++mi) {
            #pragma unroll
            for (int ni = 0; ni < 4; ++ni) {
                int r  = m0 + wm * 64 + mi * 16 + qr;
                int cc = cb + wn * 32 + ni * 8 + qc;
                float a0 = acc[mi][ni][0], a1 = acc[mi][ni][1];
                float a2 = acc[mi][ni][2], a3 = acc[mi][ni][3];
                uint32_t h01 = cvt2bf(a0, a1), h23 = cvt2bf(a2, a3);
                uint32_t l01 = cvt2bf(a0 - bflo(h01), a1 - bfhi(h01));
                uint32_t l23 = cvt2bf(a2 - bflo(h23), a3 - bfhi(h23));
                *(uint32_t*)(g_vh + (size_t)r * D_ + cc)       = h01;
                *(uint32_t*)(g_vh + (size_t)(r + 8) * D_ + cc) = h23;
                *(uint32_t*)(g_vl + (size_t)r * D_ + cc)       = l01;
                *(uint32_t*)(g_vl + (size_t)(r + 8) * D_ + cc) = l23;
            }
        }
    } else {
        #pragma unroll
        for (int mi = 0; mi < 4; ++mi) {
            #pragma unroll
            for (int ni = 0; ni < 4; ++ni) {
                int r  = m0 + wm * 64 + mi * 16 + qr;
                int cc = n0 + wn * 32 + ni * 8 + qc;
                *(float2*)(C + (size_t)r * N + cc)       = make_float2(acc[mi][ni][0], acc[mi][ni][1]);
                *(float2*)(C + (size_t)(r + 8) * N + cc) = make_float2(acc[mi][ni][2], acc[mi][ni][3]);
            }
        }
    }
}

__global__ __launch_bounds__(256, 1)
void hmma_qkv_kernel() { hmma_gemm_body<true >(g_xh, g_xl, g_wh, g_wl, g_qkv, TD); }
__global__ __launch_bounds__(256, 1)
void hmma_out_kernel(float* __restrict__ out) { hmma_gemm_body<false>(g_aoh, g_aol, g_owh, g_owl, out, D_); }

// ======================================================================
// Trajectory kernels
// ======================================================================
__global__ void traj_mag_kernel(const float* __restrict__ x)
{
    int gw   = (blockIdx.x * blockDim.x + threadIdx.x) >> 5;
    int lane = threadIdx.x & 31;
    if (gw >= B_ * (S_ - 1)) return;
    int b = gw / (S_ - 1);
    int j = gw % (S_ - 1);
    const float* r0 = x + ((size_t)b * S_ + j) * D_;
    const float* r1 = r0 + D_;
    float ss = 0.f;
    #pragma unroll
    for (int it = 0; it < D_ / (32 * 4); ++it) {
        int d = lane * 4 + it * 128;
        float4 a = *(const float4*)(r0 + d);
        float4 c = *(const float4*)(r1 + d);
        float dx = c.x - a.x, dy = c.y - a.y, dz = c.z - a.z, dw = c.w - a.w;
        ss += dx*dx + dy*dy + dz*dz + dw*dw;
    }
    #pragma unroll
    for (int o = 16; o; o >>= 1) ss += __shfl_xor_sync(0xffffffffu, ss, o);
    if (lane == 0) {
        float mag = sqrtf(ss);
        g_im[b * (S_-1) + j] = 1.0f / fmaxf(mag, 1e-8f);
        g_mw[b * (S_-1) + j] = tanhf(mag);
    }
}

__global__ void traj_out_kernel(const float* __restrict__ x, float* __restrict__ traj)
{
    int p = blockIdx.x;
    int b = blockIdx.y;
    __shared__ float coef[IR];
    __shared__ int   sh_ws, sh_cnt;
    if (threadIdx.x == 0) {
        int ws  = p - IR; if (ws < 0) ws = 0;
        int cnt = p - ws;
        float wsz = (float)(cnt > 0 ? cnt : 1);
        float w[IR]; float sum = 0.f;
        for (int t = 0; t < cnt; ++t) {
            float wv = g_mw[b * (S_-1) + ws + t] * (float)(t + 1) / wsz;
            w[t] = wv; sum += wv;
        }
        float inv = 1.0f / fmaxf(sum, 1e-8f);
        for (int t = 0; t < cnt; ++t)
            coef[t] = w[t] * inv * g_im[b * (S_-1) + ws + t];
        sh_ws = ws; sh_cnt = cnt;
    }
    __syncthreads();
    int ws = sh_ws, cnt = sh_cnt;
    const float* xb = x + (size_t)b * S_ * D_;
    for (int d = threadIdx.x * 4; d < D_; d += blockDim.x * 4) {
        float4 a = make_float4(0.f, 0.f, 0.f, 0.f);
        for (int t = 0; t < cnt; ++t) {
            float c = coef[t];
            const float* r0 = xb + (size_t)(ws + t) * D_ + d;
            float4 u = *(const float4*)(r0);
            float4 v = *(const float4*)(r0 + D_);
            a.x += c * (v.x - u.x); a.y += c * (v.y - u.y);
            a.z += c * (v.z - u.z); a.w += c * (v.w - u.w);
        }
        *(float4*)(traj + ((size_t)b * S_ + p) * D_ + d) = a;
    }
}

// ======================================================================
// Splat weights -> bf16 hi/lo directly (packed f32x2 math, fused q+k)
// ======================================================================
__global__ __launch_bounds__(256)
void splat_weights_kernel(const float* __restrict__ centers,
                          const float* __restrict__ lsc,
                          const float* __restrict__ amp)
{
    int z = blockIdx.z;
    int which = z & 1;
    int b = z >> 1;
    int h = blockIdx.y;
    int s0 = blockIdx.x * 128;
    int tid = threadIdx.x;
    int off = which ? D_ : 0;

    __shared__ __align__(16) float cs[KS][HD];
    __shared__ float cn[KS], fac[KS], am[KS];
    __shared__ __align__(16) float ts[128][HD];
    __shared__ float tn[128];

    #pragma unroll
    for (int it = 0; it < 4; ++it) {
        int idx = tid + it * 256;
        int kk = idx >> 6, d = idx & 63;
        cs[kk][d] = centers[((size_t)h * KS + kk) * HD + d];
    }
    if (tid < KS) {
        float ls = lsc[h * KS + tid];
        fac[tid] = -0.5f * __expf(-2.0f * ls);
        float a  = amp[h * KS + tid];
        am[tid]  = 1.0f / (1.0f + __expf(-a));
    }
    const float* bse = g_qkv + ((size_t)b * S_ + s0) * TD + off + h * HD;
    #pragma unroll
    for (int it = 0; it < 8; ++it) {
        int idx = tid + it * 256;
        int s = idx >> 4, c4 = (idx & 15) * 4;
        *(float4*)&ts[s][c4] = *(const float4*)(bse + (size_t)s * TD + c4);
    }
    __syncthreads();
    if (tid < KS) {
        float s = 0.f;
        #pragma unroll
        for (int d = 0; d < HD; ++d) { float c = cs[tid][d]; s += c * c; }
        cn[tid] = s;
    }
    if (tid < 128) {
        const u64* tp = (const u64*)&ts[tid][0];
        u64 acc = 0ull;
        #pragma unroll
        for (int d = 0; d < 32; ++d) acc = ffma2(tp[d], tp[d], acc);
        float2 u = up2(acc);
        tn[tid] = u.x + u.y;
    }
    __syncthreads();

    #pragma unroll
    for (int it = 0; it < 8; ++it) {
        int idx = tid + it * 256;
        int s = idx >> 4, kk = idx & 15;
        const u64* tp = (const u64*)&ts[s][0];
        const u64* cp = (const u64*)&cs[kk][0];
        u64 acc = 0ull;
        #pragma unroll
        for (int d = 0; d < 32; ++d) acc = ffma2(tp[d], cp[d], acc);
        float2 u = up2(acc);
        float cross = u.x + u.y;
        float dist = tn[s] - 2.0f * cross + cn[kk];
        float w = __expf(fac[kk] * dist) * am[kk];
        __nv_bfloat16 hh = __float2bfloat16(w);
        float hf = __bfloat162float(hh);
        __nv_bfloat16 hl = __float2bfloat16(w - hf);
        size_t o = (((size_t)b * H_ + h) * S_ + s0 + s) * KS + kk;
        if (which) { g_kwh[o] = hh; g_kwl[o] = hl; }
        else       { g_qwh[o] = hh; g_qwl[o] = hl; }
    }
}

// ======================================================================
// HMMA flash attention. CTA = 128 queries of one (b,h); 8 warps x 16 q.
// Same 64-j staged tile now amortized over 2x queries vs R9.
// ======================================================================
__global__ __launch_bounds__(256, 1)
void attn_mma_kernel()
{
    const int b = blockIdx.z, h = blockIdx.y;
    const int tid = threadIdx.x, lane = tid & 31, warp = tid >> 5;
    const int q0 = blockIdx.x * 128 + warp * 16;

    __shared__ __align__(16) __nv_bfloat16 skh[64][24];
    __shared__ __align__(16) __nv_bfloat16 skl[64][24];
    __shared__ __align__(16) __nv_bfloat16 svh[64][72];
    __shared__ __align__(16) __nv_bfloat16 svl[64][72];

    const int r4 = lane >> 2;
    const int c2 = (lane & 3) * 2;

    uint32_t qh[4], ql[4];
    {
        const __nv_bfloat16* qhb = g_qwh + (((size_t)b * H_ + h) * S_ + q0) * KS;
        const __nv_bfloat16* qlb = g_qwl + (((size_t)b * H_ + h) * S_ + q0) * KS;
        qh[0] = *(const uint32_t*)(qhb + (size_t)r4 * KS + c2);
        qh[1] = *(const uint32_t*)(qhb + (size_t)(r4 + 8) * KS + c2);
        qh[2] = *(const uint32_t*)(qhb + (size_t)r4 * KS + c2 + 8);
        qh[3] = *(const uint32_t*)(qhb + (size_t)(r4 + 8) * KS + c2 + 8);
        ql[0] = *(const uint32_t*)(qlb + (size_t)r4 * KS + c2);
        ql[1] = *(const uint32_t*)(qlb + (size_t)(r4 + 8) * KS + c2);
        ql[2] = *(const uint32_t*)(qlb + (size_t)r4 * KS + c2 + 8);
        ql[3] = *(const uint32_t*)(qlb + (size_t)(r4 + 8) * KS + c2 + 8);
    }

    float acc[8][4];
    #pragma unroll
    for (int i = 0; i < 8; ++i)
        #pragma unroll
        for (int q = 0; q < 4; ++q) acc[i][q] = 0.f;
    float den0 = 0.f, den1 = 0.f;

    const int jj  = lane >> 3, rin = lane & 7;
    const int k_row = ((jj >> 1) << 3) + rin;
    const int k_col = (jj & 1) * 8;
    const int v_row = lane & 15;
    const int v_col = (lane >> 4) * 8;

    const size_t kw_base = (((size_t)b * H_ + h) * S_) * KS;
    const size_t v_base  = ((size_t)b * S_) * D_ + h * HD;

    for (int j0 = 0; j0 < S_; j0 += 64) {
        // ---- stage kw (threads 0-127) + V (all 256) ----
        if (tid < 128) {
            int row = tid >> 1, part = tid & 1;
            size_t gk = kw_base + (size_t)(j0 + row) * KS + part * 8;
            *(uint4*)&skh[row][part * 8] = *(const uint4*)(g_kwh + gk);
            *(uint4*)&skl[row][part * 8] = *(const uint4*)(g_kwl + gk);
        }
        #pragma unroll
        for (int i = 0; i < 2; ++i) {
            int idx = tid + i * 256;
            int row = idx >> 3, seg = idx & 7;
            size_t gv = v_base + (size_t)(j0 + row) * D_ + seg * 8;
            *(uint4*)&svh[row][seg * 8] = *(const uint4*)(g_vh + gv);
            *(uint4*)&svl[row][seg * 8] = *(const uint4*)(g_vl + gv);
        }
        __syncthreads();

        #pragma unroll
        for (int jt = 0; jt < 4; ++jt) {
            uint32_t kh[4], kl[4];
            ldsm4(smem_u32(&skh[jt * 16 + k_row][k_col]), kh);
            ldsm4(smem_u32(&skl[jt * 16 + k_row][k_col]), kl);

            float cz0[4] = {0.f, 0.f, 0.f, 0.f};
            float cz1[4] = {0.f, 0.f, 0.f, 0.f};
            mma_bf16(cz0, qh, kh);
            mma_bf16(cz0, ql, kh);
            mma_bf16(cz0, qh, kl);
            mma_bf16(cz1, qh, kh + 2);
            mma_bf16(cz1, ql, kh + 2);
            mma_bf16(cz1, qh, kl + 2);

            float e00 = __expf(cz0[0]), e01 = __expf(cz0[1]);
            float e02 = __expf(cz0[2]), e03 = __expf(cz0[3]);
            float e10 = __expf(cz1[0]), e11 = __expf(cz1[1]);
            float e12 = __expf(cz1[2]), e13 = __expf(cz1[3]);
            den0 += e00 + e01 + e10 + e11;
            den1 += e02 + e03 + e12 + e13;

            uint32_t ph[4], pl[4];
            ph[0] = cvt2bf(e00, e01);
            ph[1] = cvt2bf(e02, e03);
            ph[2] = cvt2bf(e10, e11);
            ph[3] = cvt2bf(e12, e13);
            pl[0] = cvt2bf(e00 - bflo(ph[0]), e01 - bfhi(ph[0]));
            pl[1] = cvt2bf(e02 - bflo(ph[1]), e03 - bfhi(ph[1]));
            pl[2] = cvt2bf(e10 - bflo(ph[2]), e11 - bfhi(ph[2]));
            pl[3] = cvt2bf(e12 - bflo(ph[3]), e13 - bfhi(ph[3]));

            #pragma unroll
            for (int dp = 0; dp < 4; ++dp) {
                uint32_t vh[4], vl[4];
                ldsm4t(smem_u32(&svh[jt * 16 + v_row][dp * 16 + v_col]), vh);
                ldsm4t(smem_u32(&svl[jt * 16 + v_row][dp * 16 + v_col]), vl);
                mma_bf16(acc[dp * 2],     ph, vh);
                mma_bf16(acc[dp * 2],     pl, vh);
                mma_bf16(acc[dp * 2],     ph, vl);
                mma_bf16(acc[dp * 2 + 1], ph, vh + 2);
                mma_bf16(acc[dp * 2 + 1], pl, vh + 2);
                mma_bf16(acc[dp * 2 + 1], ph, vl + 2);
            }
        }
        __syncthreads();
    }

    den0 += __shfl_xor_sync(0xffffffffu, den0, 1);
    den0 += __shfl_xor_sync(0xffffffffu, den0, 2);
    den1 += __shfl_xor_sync(0xffffffffu, den1, 1);
    den1 += __shfl_xor_sync(0xffffffffu, den1, 2);
    float inv0 = 1.0f / den0;
    float inv1 = 1.0f / den1;

    size_t row_a = ((size_t)b * S_ + q0 + r4) * D_ + h * HD;
    size_t row_b = ((size_t)b * S_ + q0 + r4 + 8) * D_ + h * HD;
    #pragma unroll
    for (int db = 0; db < 8; ++db) {
        int dc = db * 8 + c2;
        float o0 = acc[db][0] * inv0, o1 = acc[db][1] * inv0;
        float o2 = acc[db][2] * inv1, o3 = acc[db][3] * inv1;
        uint32_t h01 = cvt2bf(o0, o1), h23 = cvt2bf(o2, o3);
        uint32_t l01 = cvt2bf(o0 - bflo(h01), o1 - bfhi(h01));
        uint32_t l23 = cvt2bf(o2 - bflo(h23), o3 - bfhi(h23));
        *(uint32_t*)(g_aoh + row_a + dc) = h01;
        *(uint32_t*)(g_aoh + row_b + dc) = h23;
        *(uint32_t*)(g_aol + row_a + dc) = l01;
        *(uint32_t*)(g_aol + row_b + dc) = l23;
    }
}

// ======================================================================
// launch
// ======================================================================
extern "C" void kernel_launch(void* const* d_in, const int* in_sizes, int n_in,
                              void* d_out, int out_size)
{
    const float* x       = (const float*)d_in[0];
    const float* qkv_w   = (const float*)d_in[1];
    const float* out_w   = (const float*)d_in[2];
    const float* centers = (const float*)d_in[3];
    const float* lsc     = (const float*)d_in[4];
    const float* amps    = (const float*)d_in[5];
    float* out = (float*)d_out;

    const int BSD = B_ * S_ * D_;

    // ---- input splits ----
    split_x_kernel <<<(BSD / 4 + 255) / 256, 256>>>(x);
    split_w_kernel <<<((TD * D_) / 4 + 255) / 256, 256>>>(qkv_w);
    split_ow_kernel<<<((D_ * D_) / 4 + 255) / 256, 256>>>(out_w);

    // ---- trajectories -> second half of d_out ----
    {
        int warps = B_ * (S_ - 1);
        int blocks = (warps * 32 + 127) / 128;
        traj_mag_kernel<<<blocks, 128>>>(x);
        if (out_size >= 2 * BSD) {
            traj_out_kernel<<<dim3(S_, B_), 256>>>(x, out + BSD);
        }
    }

    // ---- qkv projection (V tiles written as bf16 hi/lo directly) ----
    hmma_qkv_kernel<<<dim3(TD / 128, (B_ * S_) / 128), 256, SS_SMEM_BYTES>>>();

    // ---- splat weights (bf16 hi/lo) ----
    splat_weights_kernel<<<dim3(S_ / 128, H_, 2 * B_), 256>>>(centers, lsc, amps);

    // ---- HMMA flash attention (8 warps / 128 queries per CTA) ----
    attn_mma_kernel<<<dim3(S_ / 128, H_, B_), 256>>>();

    // ---- output projection ----
    hmma_out_kernel<<<dim3(D_ / 128, (B_ * S_) / 128), 256, SS_SMEM_BYTES>>>(out);
}

// round 14
// speedup vs baseline: 1.6297x; 1.6297x over previous
#include <cuda_runtime.h>
#include <cuda_bf16.h>
#include <math.h>
#include <stdint.h>

// ---------------- problem constants (fixed shapes) ----------------
#define B_  2
#define S_  2048
#define D_  1024
#define H_  16
#define KS  16      // splats per head
#define HD  64      // head dim
#define TD  (3*D_)  // qkv row width = 3072
#define IR  8       // influence radius
#define KDIM 1024   // GEMM K for both projections

typedef unsigned long long u64;

// ---------------- packed f32x2 helpers ----------------
__device__ __forceinline__ float2 up2(u64 v) {
    float2 r; asm("mov.b64 {%0, %1}, %2;" : "=f"(r.x), "=f"(r.y) : "l"(v)); return r;
}
__device__ __forceinline__ u64 ffma2(u64 a, u64 b, u64 c) {
    u64 d; asm("fma.rn.f32x2 %0, %1, %2, %3;" : "=l"(d) : "l"(a), "l"(b), "l"(c));
    return d;
}

// ---------------- warp MMA helpers (sm_80 baseline PTX) ----
__device__ __forceinline__ uint32_t smem_u32(const void* p) {
    uint32_t a;
    asm("{ .reg .u64 t; cvta.to.shared.u64 t, %1; cvt.u32.u64 %0, t; }" : "=r"(a) : "l"(p));
    return a;
}
__device__ __forceinline__ void ldsm4(uint32_t addr, uint32_t* r) {
    asm volatile("ldmatrix.sync.aligned.m8n8.x4.shared.b16 {%0,%1,%2,%3}, [%4];"
                 : "=r"(r[0]), "=r"(r[1]), "=r"(r[2]), "=r"(r[3]) : "r"(addr));
}
__device__ __forceinline__ void ldsm4t(uint32_t addr, uint32_t* r) {
    asm volatile("ldmatrix.sync.aligned.m8n8.x4.trans.shared.b16 {%0,%1,%2,%3}, [%4];"
                 : "=r"(r[0]), "=r"(r[1]), "=r"(r[2]), "=r"(r[3]) : "r"(addr));
}
__device__ __forceinline__ void mma_bf16(float* c, const uint32_t* a, const uint32_t* b) {
    asm volatile("mma.sync.aligned.m16n8k16.row.col.f32.bf16.bf16.f32 "
                 "{%0,%1,%2,%3}, {%4,%5,%6,%7}, {%8,%9}, {%0,%1,%2,%3};"
                 : "+f"(c[0]), "+f"(c[1]), "+f"(c[2]), "+f"(c[3])
                 : "r"(a[0]), "r"(a[1]), "r"(a[2]), "r"(a[3]), "r"(b[0]), "r"(b[1]));
}
__device__ __forceinline__ uint32_t cvt2bf(float lo, float hi) {
    uint32_t r; asm("cvt.rn.bf16x2.f32 %0, %1, %2;" : "=r"(r) : "f"(hi), "f"(lo)); return r;
}
__device__ __forceinline__ float bflo(uint32_t p) { return __uint_as_float(p << 16); }
__device__ __forceinline__ float bfhi(uint32_t p) { return __uint_as_float(p & 0xffff0000u); }

// ---------------- scratch (device globals; no allocation allowed) ----------------
// NOTE: reference these ONLY from device code (host-shadow pitfall, R6/R7).
__device__ __align__(16) float g_qkv[(size_t)B_ * S_ * TD];
__device__ float g_mw [B_ * (S_-1)];
__device__ float g_im [B_ * (S_-1)];
__device__ __align__(16) __nv_bfloat16 g_xh [(size_t)B_ * S_ * D_];
__device__ __align__(16) __nv_bfloat16 g_xl [(size_t)B_ * S_ * D_];
__device__ __align__(16) __nv_bfloat16 g_wh [(size_t)TD * D_];
__device__ __align__(16) __nv_bfloat16 g_wl [(size_t)TD * D_];
__device__ __align__(16) __nv_bfloat16 g_aoh[(size_t)B_ * S_ * D_];
__device__ __align__(16) __nv_bfloat16 g_aol[(size_t)B_ * S_ * D_];
__device__ __align__(16) __nv_bfloat16 g_owh[(size_t)D_ * D_];
__device__ __align__(16) __nv_bfloat16 g_owl[(size_t)D_ * D_];
__device__ __align__(16) __nv_bfloat16 g_qwh[(size_t)B_ * H_ * S_ * KS];
__device__ __align__(16) __nv_bfloat16 g_qwl[(size_t)B_ * H_ * S_ * KS];
__device__ __align__(16) __nv_bfloat16 g_kwh[(size_t)B_ * H_ * S_ * KS];
__device__ __align__(16) __nv_bfloat16 g_kwl[(size_t)B_ * H_ * S_ * KS];
__device__ __align__(16) __nv_bfloat16 g_vh [(size_t)B_ * S_ * D_];
__device__ __align__(16) __nv_bfloat16 g_vl [(size_t)B_ * S_ * D_];

// ======================================================================
// fp32 -> (hi, lo) bf16 split
// ======================================================================
__device__ __forceinline__ void split_body(const float* __restrict__ in,
                                           __nv_bfloat16* __restrict__ hi,
                                           __nv_bfloat16* __restrict__ lo, int n4)
{
    int i = blockIdx.x * blockDim.x + threadIdx.x;
    if (i >= n4) return;
    float4 v = ((const float4*)in)[i];
    float f[4] = {v.x, v.y, v.z, v.w};
    unsigned short hb[4], lb[4];
    #pragma unroll
    for (int j = 0; j < 4; ++j) {
        __nv_bfloat16 h = __float2bfloat16(f[j]);
        float hf = __bfloat162float(h);
        __nv_bfloat16 l = __float2bfloat16(f[j] - hf);
        hb[j] = __bfloat16_as_ushort(h);
        lb[j] = __bfloat16_as_ushort(l);
    }
    ((ushort4*)hi)[i] = make_ushort4(hb[0], hb[1], hb[2], hb[3]);
    ((ushort4*)lo)[i] = make_ushort4(lb[0], lb[1], lb[2], lb[3]);
}

__global__ __launch_bounds__(256)
void split_x_kernel(const float* __restrict__ in)
{ split_body(in, g_xh, g_xl, (B_ * S_ * D_) / 4); }

__global__ __launch_bounds__(256)
void split_w_kernel(const float* __restrict__ in)
{ split_body(in, g_wh, g_wl, (TD * D_) / 4); }

__global__ __launch_bounds__(256)
void split_ow_kernel(const float* __restrict__ in)
{ split_body(in, g_owh, g_owl, (D_ * D_) / 4); }

// ======================================================================
// HMMA split-bf16 GEMM: C[M,N] = A[M,K]*B[N,K]^T, fp32 out.
// Single-stage register-prefetch (R9-proven, fastest measured).
// WV=true (QKV gemm): tiles with n0>=2D are V -> bf16 hi/lo direct.
// ======================================================================
#define RSB   80
#define ARR_B (128 * RSB)
#define SS_SMEM_BYTES (4 * ARR_B)   // 40960 B

template<bool WV>
__device__ __forceinline__ void hmma_gemm_body(
    const __nv_bfloat16* __restrict__ Ah, const __nv_bfloat16* __restrict__ Al,
    const __nv_bfloat16* __restrict__ Bh, const __nv_bfloat16* __restrict__ Bl,
    float* __restrict__ C, int N)
{
    extern __shared__ char smem_raw[];
    const uint32_t base = smem_u32(smem_raw);

    const int tid  = threadIdx.x;
    const int lane = tid & 31;
    const int warp = tid >> 5;
    const int wm = warp >> 2;
    const int wn = warp & 3;
    const int m0 = blockIdx.y * 128;
    const int n0 = blockIdx.x * 128;

    const int j   = lane >> 3;
    const int rin = lane & 7;
    const uint32_t a_row = wm * 64 + ((j & 1) << 3) + rin;
    const uint32_t a_kb  = (j >> 1) << 4;
    const uint32_t b_row = wn * 32 + ((j >> 1) << 3) + rin;
    const uint32_t b_kb  = (j & 1) << 4;

    const int g_row0 = tid >> 2;
    const int g_cg   = tid & 3;

    float acc[4][4][4];
    #pragma unroll
    for (int mi = 0; mi < 4; ++mi)
        #pragma unroll
        for (int ni = 0; ni < 4; ++ni)
            #pragma unroll
            for (int q = 0; q < 4; ++q) acc[mi][ni][q] = 0.f;

    const __nv_bfloat16* srcs[4] = { Ah, Al, Bh, Bl };

    #pragma unroll
    for (int arr = 0; arr < 4; ++arr) {
        const __nv_bfloat16* src = srcs[arr];
        const int rbase = (arr < 2) ? m0 : n0;
        #pragma unroll
        for (int i = 0; i < 2; ++i) {
            int row = g_row0 + i * 64;
            uint4 v = *(const uint4*)(src + (size_t)(rbase + row) * KDIM + g_cg * 8);
            uint32_t sa = base + arr * ARR_B + row * RSB + g_cg * 16;
            asm volatile("st.shared.v4.b32 [%0], {%1,%2,%3,%4};"
                         :: "r"(sa), "r"(v.x), "r"(v.y), "r"(v.z), "r"(v.w) : "memory");
        }
    }
    __syncthreads();

    const int CH = KDIM / 32;
    for (int c = 0; c < CH; ++c) {
        uint4 pre[4][2];
        const bool more = (c + 1 < CH);
        if (more) {
            #pragma unroll
            for (int arr = 0; arr < 4; ++arr) {
                const __nv_bfloat16* src = srcs[arr];
                const int rbase = (arr < 2) ? m0 : n0;
                #pragma unroll
                for (int i = 0; i < 2; ++i) {
                    int row = g_row0 + i * 64;
                    pre[arr][i] = *(const uint4*)(src + (size_t)(rbase + row) * KDIM + (c + 1) * 32 + g_cg * 8);
                }
            }
        }

        #pragma unroll
        for (int ks = 0; ks < 2; ++ks) {
            const uint32_t kbo = ks * 32;
            uint32_t ah[4][4], al[4][4], bh[4][2], bl[4][2];
            #pragma unroll
            for (int mi = 0; mi < 4; ++mi) {
                uint32_t addr = base + (a_row + mi * 16) * RSB + kbo + a_kb;
                ldsm4(addr, ah[mi]);
                ldsm4(addr + ARR_B, al[mi]);
            }
            #pragma unroll
            for (int p = 0; p < 2; ++p) {
                uint32_t addr = base + 2 * ARR_B + (b_row + p * 16) * RSB + kbo + b_kb;
                uint32_t rh[4], rl[4];
                ldsm4(addr, rh);
                ldsm4(addr + ARR_B, rl);
                bh[p*2+0][0] = rh[0]; bh[p*2+0][1] = rh[1];
                bh[p*2+1][0] = rh[2]; bh[p*2+1][1] = rh[3];
                bl[p*2+0][0] = rl[0]; bl[p*2+0][1] = rl[1];
                bl[p*2+1][0] = rl[2]; bl[p*2+1][1] = rl[3];
            }
            #pragma unroll
            for (int mi = 0; mi < 4; ++mi)
                #pragma unroll
                for (int ni = 0; ni < 4; ++ni) {
                    mma_bf16(acc[mi][ni], ah[mi], bh[ni]);
                    mma_bf16(acc[mi][ni], al[mi], bh[ni]);
                    mma_bf16(acc[mi][ni], ah[mi], bl[ni]);
                }
        }
        __syncthreads();

        if (more) {
            #pragma unroll
            for (int arr = 0; arr < 4; ++arr)
                #pragma unroll
                for (int i = 0; i < 2; ++i) {
                    int row = g_row0 + i * 64;
                    uint32_t sa = base + arr * ARR_B + row * RSB + g_cg * 16;
                    uint4 v = pre[arr][i];
                    asm volatile("st.shared.v4.b32 [%0], {%1,%2,%3,%4};"
                                 :: "r"(sa), "r"(v.x), "r"(v.y), "r"(v.z), "r"(v.w) : "memory");
                }
            __syncthreads();
        }
    }

    const int qr = lane >> 2;
    const int qc = (lane & 3) * 2;
    if (WV && n0 >= 2 * D_) {
        // V tile: write bf16 hi/lo splits directly (replaces split_v)
        const int cb = n0 - 2 * D_;
        #pragma unroll
        for (int mi = 0; mi < 4; ++mi) {
            #pragma unroll
            for (int ni = 0; ni < 4; ++ni) {
                int r  = m0 + wm * 64 + mi * 16 + qr;
                int cc = cb + wn * 32 + ni * 8 + qc;
                float a0 = acc[mi][ni][0], a1 = acc[mi][ni][1];
                float a2 = acc[mi][ni][2], a3 = acc[mi][ni][3];
                uint32_t h01 = cvt2bf(a0, a1), h23 = cvt2bf(a2, a3);
                uint32_t l01 = cvt2bf(a0 - bflo(h01), a1 - bfhi(h01));
                uint32_t l23 = cvt2bf(a2 - bflo(h23), a3 - bfhi(h23));
                *(uint32_t*)(g_vh + (size_t)r * D_ + cc)       = h01;
                *(uint32_t*)(g_vh + (size_t)(r + 8) * D_ + cc) = h23;
                *(uint32_t*)(g_vl + (size_t)r * D_ + cc)       = l01;
                *(uint32_t*)(g_vl + (size_t)(r + 8) * D_ + cc) = l23;
            }
        }
    } else {
        #pragma unroll
        for (int mi = 0; mi < 4; ++mi) {
            #pragma unroll
            for (int ni = 0; ni < 4; ++ni) {
                int r  = m0 + wm * 64 + mi * 16 + qr;
                int cc = n0 + wn * 32 + ni * 8 + qc;
                *(float2*)(C + (size_t)r * N + cc)       = make_float2(acc[mi][ni][0], acc[mi][ni][1]);
                *(float2*)(C + (size_t)(r + 8) * N + cc) = make_float2(acc[mi][ni][2], acc[mi][ni][3]);
            }
        }
    }
}

__global__ __launch_bounds__(256, 1)
void hmma_qkv_kernel() { hmma_gemm_body<true >(g_xh, g_xl, g_wh, g_wl, g_qkv, TD); }
__global__ __launch_bounds__(256, 1)
void hmma_out_kernel(float* __restrict__ out) { hmma_gemm_body<false>(g_aoh, g_aol, g_owh, g_owl, out, D_); }

// ======================================================================
// Trajectory kernels
// ======================================================================
__global__ void traj_mag_kernel(const float* __restrict__ x)
{
    int gw   = (blockIdx.x * blockDim.x + threadIdx.x) >> 5;
    int lane = threadIdx.x & 31;
    if (gw >= B_ * (S_ - 1)) return;
    int b = gw / (S_ - 1);
    int j = gw % (S_ - 1);
    const float* r0 = x + ((size_t)b * S_ + j) * D_;
    const float* r1 = r0 + D_;
    float ss = 0.f;
    #pragma unroll
    for (int it = 0; it < D_ / (32 * 4); ++it) {
        int d = lane * 4 + it * 128;
        float4 a = *(const float4*)(r0 + d);
        float4 c = *(const float4*)(r1 + d);
        float dx = c.x - a.x, dy = c.y - a.y, dz = c.z - a.z, dw = c.w - a.w;
        ss += dx*dx + dy*dy + dz*dz + dw*dw;
    }
    #pragma unroll
    for (int o = 16; o; o >>= 1) ss += __shfl_xor_sync(0xffffffffu, ss, o);
    if (lane == 0) {
        float mag = sqrtf(ss);
        g_im[b * (S_-1) + j] = 1.0f / fmaxf(mag, 1e-8f);
        g_mw[b * (S_-1) + j] = tanhf(mag);
    }
}

__global__ void traj_out_kernel(const float* __restrict__ x, float* __restrict__ traj)
{
    int p = blockIdx.x;
    int b = blockIdx.y;
    __shared__ float coef[IR];
    __shared__ int   sh_ws, sh_cnt;
    if (threadIdx.x == 0) {
        int ws  = p - IR; if (ws < 0) ws = 0;
        int cnt = p - ws;
        float wsz = (float)(cnt > 0 ? cnt : 1);
        float w[IR]; float sum = 0.f;
        for (int t = 0; t < cnt; ++t) {
            float wv = g_mw[b * (S_-1) + ws + t] * (float)(t + 1) / wsz;
            w[t] = wv; sum += wv;
        }
        float inv = 1.0f / fmaxf(sum, 1e-8f);
        for (int t = 0; t < cnt; ++t)
            coef[t] = w[t] * inv * g_im[b * (S_-1) + ws + t];
        sh_ws = ws; sh_cnt = cnt;
    }
    __syncthreads();
    int ws = sh_ws, cnt = sh_cnt;
    const float* xb = x + (size_t)b * S_ * D_;
    for (int d = threadIdx.x * 4; d < D_; d += blockDim.x * 4) {
        float4 a = make_float4(0.f, 0.f, 0.f, 0.f);
        for (int t = 0; t < cnt; ++t) {
            float c = coef[t];
            const float* r0 = xb + (size_t)(ws + t) * D_ + d;
            float4 u = *(const float4*)(r0);
            float4 v = *(const float4*)(r0 + D_);
            a.x += c * (v.x - u.x); a.y += c * (v.y - u.y);
            a.z += c * (v.z - u.z); a.w += c * (v.w - u.w);
        }
        *(float4*)(traj + ((size_t)b * S_ + p) * D_ + d) = a;
    }
}

// ======================================================================
// Splat weights -> bf16 hi/lo directly (packed f32x2 math, fused q+k)
// ======================================================================
__global__ __launch_bounds__(256)
void splat_weights_kernel(const float* __restrict__ centers,
                          const float* __restrict__ lsc,
                          const float* __restrict__ amp)
{
    int z = blockIdx.z;
    int which = z & 1;
    int b = z >> 1;
    int h = blockIdx.y;
    int s0 = blockIdx.x * 128;
    int tid = threadIdx.x;
    int off = which ? D_ : 0;

    __shared__ __align__(16) float cs[KS][HD];
    __shared__ float cn[KS], fac[KS], am[KS];
    __shared__ __align__(16) float ts[128][HD];
    __shared__ float tn[128];

    #pragma unroll
    for (int it = 0; it < 4; ++it) {
        int idx = tid + it * 256;
        int kk = idx >> 6, d = idx & 63;
        cs[kk][d] = centers[((size_t)h * KS + kk) * HD + d];
    }
    if (tid < KS) {
        float ls = lsc[h * KS + tid];
        fac[tid] = -0.5f * __expf(-2.0f * ls);
        float a  = amp[h * KS + tid];
        am[tid]  = 1.0f / (1.0f + __expf(-a));
    }
    const float* bse = g_qkv + ((size_t)b * S_ + s0) * TD + off + h * HD;
    #pragma unroll
    for (int it = 0; it < 8; ++it) {
        int idx = tid + it * 256;
        int s = idx >> 4, c4 = (idx & 15) * 4;
        *(float4*)&ts[s][c4] = *(const float4*)(bse + (size_t)s * TD + c4);
    }
    __syncthreads();
    if (tid < KS) {
        float s = 0.f;
        #pragma unroll
        for (int d = 0; d < HD; ++d) { float c = cs[tid][d]; s += c * c; }
        cn[tid] = s;
    }
    if (tid < 128) {
        const u64* tp = (const u64*)&ts[tid][0];
        u64 acc = 0ull;
        #pragma unroll
        for (int d = 0; d < 32; ++d) acc = ffma2(tp[d], tp[d], acc);
        float2 u = up2(acc);
        tn[tid] = u.x + u.y;
    }
    __syncthreads();

    #pragma unroll
    for (int it = 0; it < 8; ++it) {
        int idx = tid + it * 256;
        int s = idx >> 4, kk = idx & 15;
        const u64* tp = (const u64*)&ts[s][0];
        const u64* cp = (const u64*)&cs[kk][0];
        u64 acc = 0ull;
        #pragma unroll
        for (int d = 0; d < 32; ++d) acc = ffma2(tp[d], cp[d], acc);
        float2 u = up2(acc);
        float cross = u.x + u.y;
        float dist = tn[s] - 2.0f * cross + cn[kk];
        float w = __expf(fac[kk] * dist) * am[kk];
        __nv_bfloat16 hh = __float2bfloat16(w);
        float hf = __bfloat162float(hh);
        __nv_bfloat16 hl = __float2bfloat16(w - hf);
        size_t o = (((size_t)b * H_ + h) * S_ + s0 + s) * KS + kk;
        if (which) { g_kwh[o] = hh; g_kwl[o] = hl; }
        else       { g_qwh[o] = hh; g_qwl[o] = hl; }
    }
}

// ======================================================================
// HMMA flash attention. CTA = 64 queries of one (b,h); 4 warps x 16 q.
// (R9-proven configuration — 8-warp variant measured much slower.)
// ======================================================================
__global__ __launch_bounds__(128, 1)
void attn_mma_kernel()
{
    const int b = blockIdx.z, h = blockIdx.y;
    const int tid = threadIdx.x, lane = tid & 31, warp = tid >> 5;
    const int q0 = blockIdx.x * 64 + warp * 16;

    __shared__ __align__(16) __nv_bfloat16 skh[64][24];
    __shared__ __align__(16) __nv_bfloat16 skl[64][24];
    __shared__ __align__(16) __nv_bfloat16 svh[64][72];
    __shared__ __align__(16) __nv_bfloat16 svl[64][72];

    const int r4 = lane >> 2;
    const int c2 = (lane & 3) * 2;

    uint32_t qh[4], ql[4];
    {
        const __nv_bfloat16* qhb = g_qwh + (((size_t)b * H_ + h) * S_ + q0) * KS;
        const __nv_bfloat16* qlb = g_qwl + (((size_t)b * H_ + h) * S_ + q0) * KS;
        qh[0] = *(const uint32_t*)(qhb + (size_t)r4 * KS + c2);
        qh[1] = *(const uint32_t*)(qhb + (size_t)(r4 + 8) * KS + c2);
        qh[2] = *(const uint32_t*)(qhb + (size_t)r4 * KS + c2 + 8);
        qh[3] = *(const uint32_t*)(qhb + (size_t)(r4 + 8) * KS + c2 + 8);
        ql[0] = *(const uint32_t*)(qlb + (size_t)r4 * KS + c2);
        ql[1] = *(const uint32_t*)(qlb + (size_t)(r4 + 8) * KS + c2);
        ql[2] = *(const uint32_t*)(qlb + (size_t)r4 * KS + c2 + 8);
        ql[3] = *(const uint32_t*)(qlb + (size_t)(r4 + 8) * KS + c2 + 8);
    }

    float acc[8][4];
    #pragma unroll
    for (int i = 0; i < 8; ++i)
        #pragma unroll
        for (int q = 0; q < 4; ++q) acc[i][q] = 0.f;
    float den0 = 0.f, den1 = 0.f;

    const int jj  = lane >> 3, rin = lane & 7;
    const int k_row = ((jj >> 1) << 3) + rin;
    const int k_col = (jj & 1) * 8;
    const int v_row = lane & 15;
    const int v_col = (lane >> 4) * 8;

    const size_t kw_base = (((size_t)b * H_ + h) * S_) * KS;
    const size_t v_base  = ((size_t)b * S_) * D_ + h * HD;

    for (int j0 = 0; j0 < S_; j0 += 64) {
        {
            int row = tid >> 1, part = tid & 1;
            size_t gk = kw_base + (size_t)(j0 + row) * KS + part * 8;
            *(uint4*)&skh[row][part * 8] = *(const uint4*)(g_kwh + gk);
            *(uint4*)&skl[row][part * 8] = *(const uint4*)(g_kwl + gk);
        }
        #pragma unroll
        for (int i = 0; i < 4; ++i) {
            int idx = tid + i * 128;
            int row = idx >> 3, seg = idx & 7;
            size_t gv = v_base + (size_t)(j0 + row) * D_ + seg * 8;
            *(uint4*)&svh[row][seg * 8] = *(const uint4*)(g_vh + gv);
            *(uint4*)&svl[row][seg * 8] = *(const uint4*)(g_vl + gv);
        }
        __syncthreads();

        #pragma unroll
        for (int jt = 0; jt < 4; ++jt) {
            uint32_t kh[4], kl[4];
            ldsm4(smem_u32(&skh[jt * 16 + k_row][k_col]), kh);
            ldsm4(smem_u32(&skl[jt * 16 + k_row][k_col]), kl);

            float cz0[4] = {0.f, 0.f, 0.f, 0.f};
            float cz1[4] = {0.f, 0.f, 0.f, 0.f};
            mma_bf16(cz0, qh, kh);
            mma_bf16(cz0, ql, kh);
            mma_bf16(cz0, qh, kl);
            mma_bf16(cz1, qh, kh + 2);
            mma_bf16(cz1, ql, kh + 2);
            mma_bf16(cz1, qh, kl + 2);

            float e00 = __expf(cz0[0]), e01 = __expf(cz0[1]);
            float e02 = __expf(cz0[2]), e03 = __expf(cz0[3]);
            float e10 = __expf(cz1[0]), e11 = __expf(cz1[1]);
            float e12 = __expf(cz1[2]), e13 = __expf(cz1[3]);
            den0 += e00 + e01 + e10 + e11;
            den1 += e02 + e03 + e12 + e13;

            uint32_t ph[4], pl[4];
            ph[0] = cvt2bf(e00, e01);
            ph[1] = cvt2bf(e02, e03);
            ph[2] = cvt2bf(e10, e11);
            ph[3] = cvt2bf(e12, e13);
            pl[0] = cvt2bf(e00 - bflo(ph[0]), e01 - bfhi(ph[0]));
            pl[1] = cvt2bf(e02 - bflo(ph[1]), e03 - bfhi(ph[1]));
            pl[2] = cvt2bf(e10 - bflo(ph[2]), e11 - bfhi(ph[2]));
            pl[3] = cvt2bf(e12 - bflo(ph[3]), e13 - bfhi(ph[3]));

            #pragma unroll
            for (int dp = 0; dp < 4; ++dp) {
                uint32_t vh[4], vl[4];
                ldsm4t(smem_u32(&svh[jt * 16 + v_row][dp * 16 + v_col]), vh);
                ldsm4t(smem_u32(&svl[jt * 16 + v_row][dp * 16 + v_col]), vl);
                mma_bf16(acc[dp * 2],     ph, vh);
                mma_bf16(acc[dp * 2],     pl, vh);
                mma_bf16(acc[dp * 2],     ph, vl);
                mma_bf16(acc[dp * 2 + 1], ph, vh + 2);
                mma_bf16(acc[dp * 2 + 1], pl, vh + 2);
                mma_bf16(acc[dp * 2 + 1], ph, vl + 2);
            }
        }
        __syncthreads();
    }

    den0 += __shfl_xor_sync(0xffffffffu, den0, 1);
    den0 += __shfl_xor_sync(0xffffffffu, den0, 2);
    den1 += __shfl_xor_sync(0xffffffffu, den1, 1);
    den1 += __shfl_xor_sync(0xffffffffu, den1, 2);
    float inv0 = 1.0f / den0;
    float inv1 = 1.0f / den1;

    size_t row_a = ((size_t)b * S_ + q0 + r4) * D_ + h * HD;
    size_t row_b = ((size_t)b * S_ + q0 + r4 + 8) * D_ + h * HD;
    #pragma unroll
    for (int db = 0; db < 8; ++db) {
        int dc = db * 8 + c2;
        float o0 = acc[db][0] * inv0, o1 = acc[db][1] * inv0;
        float o2 = acc[db][2] * inv1, o3 = acc[db][3] * inv1;
        uint32_t h01 = cvt2bf(o0, o1), h23 = cvt2bf(o2, o3);
        uint32_t l01 = cvt2bf(o0 - bflo(h01), o1 - bfhi(h01));
        uint32_t l23 = cvt2bf(o2 - bflo(h23), o3 - bfhi(h23));
        *(uint32_t*)(g_aoh + row_a + dc) = h01;
        *(uint32_t*)(g_aoh + row_b + dc) = h23;
        *(uint32_t*)(g_aol + row_a + dc) = l01;
        *(uint32_t*)(g_aol + row_b + dc) = l23;
    }
}

// ======================================================================
// launch
// ======================================================================
extern "C" void kernel_launch(void* const* d_in, const int* in_sizes, int n_in,
                              void* d_out, int out_size)
{
    const float* x       = (const float*)d_in[0];
    const float* qkv_w   = (const float*)d_in[1];
    const float* out_w   = (const float*)d_in[2];
    const float* centers = (const float*)d_in[3];
    const float* lsc     = (const float*)d_in[4];
    const float* amps    = (const float*)d_in[5];
    float* out = (float*)d_out;

    const int BSD = B_ * S_ * D_;

    // ---- input splits ----
    split_x_kernel <<<(BSD / 4 + 255) / 256, 256>>>(x);
    split_w_kernel <<<((TD * D_) / 4 + 255) / 256, 256>>>(qkv_w);
    split_ow_kernel<<<((D_ * D_) / 4 + 255) / 256, 256>>>(out_w);

    // ---- trajectories -> second half of d_out ----
    {
        int warps = B_ * (S_ - 1);
        int blocks = (warps * 32 + 127) / 128;
        traj_mag_kernel<<<blocks, 128>>>(x);
        if (out_size >= 2 * BSD) {
            traj_out_kernel<<<dim3(S_, B_), 256>>>(x, out + BSD);
        }
    }

    // ---- qkv projection (V tiles written as bf16 hi/lo directly) ----
    hmma_qkv_kernel<<<dim3(TD / 128, (B_ * S_) / 128), 256, SS_SMEM_BYTES>>>();

    // ---- splat weights (bf16 hi/lo) ----
    splat_weights_kernel<<<dim3(S_ / 128, H_, 2 * B_), 256>>>(centers, lsc, amps);

    // ---- HMMA flash attention (4 warps / 64 queries per CTA) ----
    attn_mma_kernel<<<dim3(S_ / 64, H_, B_), 128>>>();

    // ---- output projection ----
    hmma_out_kernel<<<dim3(D_ / 128, (B_ * S_) / 128), 256, SS_SMEM_BYTES>>>(out);
}

// round 15
// speedup vs baseline: 1.6782x; 1.0297x over previous
#include <cuda_runtime.h>
#include <cuda_bf16.h>
#include <math.h>
#include <stdint.h>

// ---------------- problem constants (fixed shapes) ----------------
#define B_  2
#define S_  2048
#define D_  1024
#define H_  16
#define KS  16      // splats per head
#define HD  64      // head dim
#define TD  (3*D_)  // qkv row width = 3072
#define IR  8       // influence radius
#define KDIM 1024   // GEMM K for both projections

typedef unsigned long long u64;

// ---------------- packed f32x2 helpers ----------------
__device__ __forceinline__ float2 up2(u64 v) {
    float2 r; asm("mov.b64 {%0, %1}, %2;" : "=f"(r.x), "=f"(r.y) : "l"(v)); return r;
}
__device__ __forceinline__ u64 ffma2(u64 a, u64 b, u64 c) {
    u64 d; asm("fma.rn.f32x2 %0, %1, %2, %3;" : "=l"(d) : "l"(a), "l"(b), "l"(c));
    return d;
}

// ---------------- warp MMA helpers (sm_80 baseline PTX) ----
__device__ __forceinline__ uint32_t smem_u32(const void* p) {
    uint32_t a;
    asm("{ .reg .u64 t; cvta.to.shared.u64 t, %1; cvt.u32.u64 %0, t; }" : "=r"(a) : "l"(p));
    return a;
}
__device__ __forceinline__ void ldsm4(uint32_t addr, uint32_t* r) {
    asm volatile("ldmatrix.sync.aligned.m8n8.x4.shared.b16 {%0,%1,%2,%3}, [%4];"
                 : "=r"(r[0]), "=r"(r[1]), "=r"(r[2]), "=r"(r[3]) : "r"(addr));
}
__device__ __forceinline__ void ldsm4t(uint32_t addr, uint32_t* r) {
    asm volatile("ldmatrix.sync.aligned.m8n8.x4.trans.shared.b16 {%0,%1,%2,%3}, [%4];"
                 : "=r"(r[0]), "=r"(r[1]), "=r"(r[2]), "=r"(r[3]) : "r"(addr));
}
__device__ __forceinline__ void mma_bf16(float* c, const uint32_t* a, const uint32_t* b) {
    asm volatile("mma.sync.aligned.m16n8k16.row.col.f32.bf16.bf16.f32 "
                 "{%0,%1,%2,%3}, {%4,%5,%6,%7}, {%8,%9}, {%0,%1,%2,%3};"
                 : "+f"(c[0]), "+f"(c[1]), "+f"(c[2]), "+f"(c[3])
                 : "r"(a[0]), "r"(a[1]), "r"(a[2]), "r"(a[3]), "r"(b[0]), "r"(b[1]));
}
__device__ __forceinline__ uint32_t cvt2bf(float lo, float hi) {
    uint32_t r; asm("cvt.rn.bf16x2.f32 %0, %1, %2;" : "=r"(r) : "f"(hi), "f"(lo)); return r;
}
__device__ __forceinline__ float bflo(uint32_t p) { return __uint_as_float(p << 16); }
__device__ __forceinline__ float bfhi(uint32_t p) { return __uint_as_float(p & 0xffff0000u); }

// ---------------- scratch (device globals; no allocation allowed) ----------------
// NOTE: reference these ONLY from device code (host-shadow pitfall, R6/R7).
__device__ __align__(16) float g_qkv[(size_t)B_ * S_ * TD];
__device__ float g_mw [B_ * (S_-1)];
__device__ float g_im [B_ * (S_-1)];
__device__ __align__(16) __nv_bfloat16 g_xh [(size_t)B_ * S_ * D_];
__device__ __align__(16) __nv_bfloat16 g_xl [(size_t)B_ * S_ * D_];
__device__ __align__(16) __nv_bfloat16 g_wh [(size_t)TD * D_];
__device__ __align__(16) __nv_bfloat16 g_wl [(size_t)TD * D_];
__device__ __align__(16) __nv_bfloat16 g_aoh[(size_t)B_ * S_ * D_];
__device__ __align__(16) __nv_bfloat16 g_aol[(size_t)B_ * S_ * D_];
__device__ __align__(16) __nv_bfloat16 g_owh[(size_t)D_ * D_];
__device__ __align__(16) __nv_bfloat16 g_owl[(size_t)D_ * D_];
__device__ __align__(16) __nv_bfloat16 g_qwh[(size_t)B_ * H_ * S_ * KS];
__device__ __align__(16) __nv_bfloat16 g_qwl[(size_t)B_ * H_ * S_ * KS];
__device__ __align__(16) __nv_bfloat16 g_kwh[(size_t)B_ * H_ * S_ * KS];
__device__ __align__(16) __nv_bfloat16 g_kwl[(size_t)B_ * H_ * S_ * KS];
__device__ __align__(16) __nv_bfloat16 g_vh [(size_t)B_ * S_ * D_];
__device__ __align__(16) __nv_bfloat16 g_vl [(size_t)B_ * S_ * D_];

// ======================================================================
// fp32 -> (hi, lo) bf16 split — all three inputs in ONE launch
// ======================================================================
#define NX4 ((B_ * S_ * D_) / 4)     // 1048576 -> 4096 blocks
#define NW4 ((TD * D_) / 4)          //  786432 -> 3072 blocks
#define NO4 ((D_ * D_) / 4)          //  262144 -> 1024 blocks

__device__ __forceinline__ void split_one(const float* __restrict__ in,
                                          __nv_bfloat16* __restrict__ hi,
                                          __nv_bfloat16* __restrict__ lo, int i)
{
    float4 v = ((const float4*)in)[i];
    float f[4] = {v.x, v.y, v.z, v.w};
    unsigned short hb[4], lb[4];
    #pragma unroll
    for (int j = 0; j < 4; ++j) {
        __nv_bfloat16 h = __float2bfloat16(f[j]);
        float hf = __bfloat162float(h);
        __nv_bfloat16 l = __float2bfloat16(f[j] - hf);
        hb[j] = __bfloat16_as_ushort(h);
        lb[j] = __bfloat16_as_ushort(l);
    }
    ((ushort4*)hi)[i] = make_ushort4(hb[0], hb[1], hb[2], hb[3]);
    ((ushort4*)lo)[i] = make_ushort4(lb[0], lb[1], lb[2], lb[3]);
}

__global__ __launch_bounds__(256)
void split_all_kernel(const float* __restrict__ x,
                      const float* __restrict__ w,
                      const float* __restrict__ ow)
{
    int gi = blockIdx.x * 256 + threadIdx.x;
    if (gi < NX4) {
        split_one(x, g_xh, g_xl, gi);
    } else if (gi < NX4 + NW4) {
        split_one(w, g_wh, g_wl, gi - NX4);
    } else {
        split_one(ow, g_owh, g_owl, gi - NX4 - NW4);
    }
}

// ======================================================================
// HMMA split-bf16 GEMM: C[M,N] = A[M,K]*B[N,K]^T, fp32 out.
// Single stage, NO register prefetch -> ~124 regs -> 2 CTAs/SM
// (launch_bounds(256,2)); cross-CTA overlap hides the per-chunk load.
// WV=true (QKV gemm): tiles with n0>=2D are V -> bf16 hi/lo direct.
// ======================================================================
#define RSB   80
#define ARR_B (128 * RSB)
#define SS_SMEM_BYTES (4 * ARR_B)   // 40960 B

template<bool WV>
__device__ __forceinline__ void hmma_gemm_body(
    const __nv_bfloat16* __restrict__ Ah, const __nv_bfloat16* __restrict__ Al,
    const __nv_bfloat16* __restrict__ Bh, const __nv_bfloat16* __restrict__ Bl,
    float* __restrict__ C, int N)
{
    extern __shared__ char smem_raw[];
    const uint32_t base = smem_u32(smem_raw);

    const int tid  = threadIdx.x;
    const int lane = tid & 31;
    const int warp = tid >> 5;
    const int wm = warp >> 2;
    const int wn = warp & 3;
    const int m0 = blockIdx.y * 128;
    const int n0 = blockIdx.x * 128;

    const int j   = lane >> 3;
    const int rin = lane & 7;
    const uint32_t a_row = wm * 64 + ((j & 1) << 3) + rin;
    const uint32_t a_kb  = (j >> 1) << 4;
    const uint32_t b_row = wn * 32 + ((j >> 1) << 3) + rin;
    const uint32_t b_kb  = (j & 1) << 4;

    const int g_row0 = tid >> 2;
    const int g_cg   = tid & 3;

    float acc[4][4][4];
    #pragma unroll
    for (int mi = 0; mi < 4; ++mi)
        #pragma unroll
        for (int ni = 0; ni < 4; ++ni)
            #pragma unroll
            for (int q = 0; q < 4; ++q) acc[mi][ni][q] = 0.f;

    const __nv_bfloat16* srcs[4] = { Ah, Al, Bh, Bl };

    const int CH = KDIM / 32;
    for (int c = 0; c < CH; ++c) {
        if (c) __syncthreads();          // prior compute done before overwrite
        #pragma unroll
        for (int arr = 0; arr < 4; ++arr) {
            const __nv_bfloat16* src = srcs[arr];
            const int rbase = (arr < 2) ? m0 : n0;
            #pragma unroll
            for (int i = 0; i < 2; ++i) {
                int row = g_row0 + i * 64;
                uint4 v = *(const uint4*)(src + (size_t)(rbase + row) * KDIM + c * 32 + g_cg * 8);
                uint32_t sa = base + arr * ARR_B + row * RSB + g_cg * 16;
                asm volatile("st.shared.v4.b32 [%0], {%1,%2,%3,%4};"
                             :: "r"(sa), "r"(v.x), "r"(v.y), "r"(v.z), "r"(v.w) : "memory");
            }
        }
        __syncthreads();

        #pragma unroll
        for (int ks = 0; ks < 2; ++ks) {
            const uint32_t kbo = ks * 32;
            uint32_t ah[4][4], al[4][4], bh[4][2], bl[4][2];
            #pragma unroll
            for (int mi = 0; mi < 4; ++mi) {
                uint32_t addr = base + (a_row + mi * 16) * RSB + kbo + a_kb;
                ldsm4(addr, ah[mi]);
                ldsm4(addr + ARR_B, al[mi]);
            }
            #pragma unroll
            for (int p = 0; p < 2; ++p) {
                uint32_t addr = base + 2 * ARR_B + (b_row + p * 16) * RSB + kbo + b_kb;
                uint32_t rh[4], rl[4];
                ldsm4(addr, rh);
                ldsm4(addr + ARR_B, rl);
                bh[p*2+0][0] = rh[0]; bh[p*2+0][1] = rh[1];
                bh[p*2+1][0] = rh[2]; bh[p*2+1][1] = rh[3];
                bl[p*2+0][0] = rl[0]; bl[p*2+0][1] = rl[1];
                bl[p*2+1][0] = rl[2]; bl[p*2+1][1] = rl[3];
            }
            #pragma unroll
            for (int mi = 0; mi < 4; ++mi)
                #pragma unroll
                for (int ni = 0; ni < 4; ++ni) {
                    mma_bf16(acc[mi][ni], ah[mi], bh[ni]);
                    mma_bf16(acc[mi][ni], al[mi], bh[ni]);
                    mma_bf16(acc[mi][ni], ah[mi], bl[ni]);
                }
        }
    }

    const int qr = lane >> 2;
    const int qc = (lane & 3) * 2;
    if (WV && n0 >= 2 * D_) {
        // V tile: write bf16 hi/lo splits directly (replaces split_v)
        const int cb = n0 - 2 * D_;
        #pragma unroll
        for (int mi = 0; mi < 4; ++mi) {
            #pragma unroll
            for (int ni = 0; ni < 4; ++ni) {
                int r  = m0 + wm * 64 + mi * 16 + qr;
                int cc = cb + wn * 32 + ni * 8 + qc;
                float a0 = acc[mi][ni][0], a1 = acc[mi][ni][1];
                float a2 = acc[mi][ni][2], a3 = acc[mi][ni][3];
                uint32_t h01 = cvt2bf(a0, a1), h23 = cvt2bf(a2, a3);
                uint32_t l01 = cvt2bf(a0 - bflo(h01), a1 - bfhi(h01));
                uint32_t l23 = cvt2bf(a2 - bflo(h23), a3 - bfhi(h23));
                *(uint32_t*)(g_vh + (size_t)r * D_ + cc)       = h01;
                *(uint32_t*)(g_vh + (size_t)(r + 8) * D_ + cc) = h23;
                *(uint32_t*)(g_vl + (size_t)r * D_ + cc)       = l01;
                *(uint32_t*)(g_vl + (size_t)(r + 8) * D_ + cc) = l23;
            }
        }
    } else {
        #pragma unroll
        for (int mi = 0; mi < 4; ++mi) {
            #pragma unroll
            for (int ni = 0; ni < 4; ++ni) {
                int r  = m0 + wm * 64 + mi * 16 + qr;
                int cc = n0 + wn * 32 + ni * 8 + qc;
                *(float2*)(C + (size_t)r * N + cc)       = make_float2(acc[mi][ni][0], acc[mi][ni][1]);
                *(float2*)(C + (size_t)(r + 8) * N + cc) = make_float2(acc[mi][ni][2], acc[mi][ni][3]);
            }
        }
    }
}

__global__ __launch_bounds__(256, 2)
void hmma_qkv_kernel() { hmma_gemm_body<true >(g_xh, g_xl, g_wh, g_wl, g_qkv, TD); }
__global__ __launch_bounds__(256, 2)
void hmma_out_kernel(float* __restrict__ out) { hmma_gemm_body<false>(g_aoh, g_aol, g_owh, g_owl, out, D_); }

// ======================================================================
// Trajectory kernels
// ======================================================================
__global__ void traj_mag_kernel(const float* __restrict__ x)
{
    int gw   = (blockIdx.x * blockDim.x + threadIdx.x) >> 5;
    int lane = threadIdx.x & 31;
    if (gw >= B_ * (S_ - 1)) return;
    int b = gw / (S_ - 1);
    int j = gw % (S_ - 1);
    const float* r0 = x + ((size_t)b * S_ + j) * D_;
    const float* r1 = r0 + D_;
    float ss = 0.f;
    #pragma unroll
    for (int it = 0; it < D_ / (32 * 4); ++it) {
        int d = lane * 4 + it * 128;
        float4 a = *(const float4*)(r0 + d);
        float4 c = *(const float4*)(r1 + d);
        float dx = c.x - a.x, dy = c.y - a.y, dz = c.z - a.z, dw = c.w - a.w;
        ss += dx*dx + dy*dy + dz*dz + dw*dw;
    }
    #pragma unroll
    for (int o = 16; o; o >>= 1) ss += __shfl_xor_sync(0xffffffffu, ss, o);
    if (lane == 0) {
        float mag = sqrtf(ss);
        g_im[b * (S_-1) + j] = 1.0f / fmaxf(mag, 1e-8f);
        g_mw[b * (S_-1) + j] = tanhf(mag);
    }
}

// Tiled traj_out: block = 16 positions x 256-d slice; shares the <=23
// needed difference rows via smem (cuts redundant x reads ~5x).
#define TP  16
#define TDW 256
__global__ __launch_bounds__(256)
void traj_out_kernel(const float* __restrict__ x, float* __restrict__ traj)
{
    const int p0 = blockIdx.x * TP;
    const int d0 = blockIdx.y * TDW;
    const int b  = blockIdx.z;
    const int tid = threadIdx.x;

    __shared__ __align__(16) float sdiff[TP + 7][TDW];   // rows base..base+22
    __shared__ float scoef[TP][IR];

    const int base = p0 - IR;   // may be negative
    const float* xb = x + (size_t)b * S_ * D_;

    // load 23 diff rows (zero where out of range)
    for (int i = tid; i < 23 * (TDW / 4); i += 256) {
        int row = i / (TDW / 4);
        int c4  = (i % (TDW / 4)) * 4;
        int jr  = base + row;              // uses x[jr], x[jr+1]
        float4 dv = make_float4(0.f, 0.f, 0.f, 0.f);
        if (jr >= 0 && jr < S_ - 1) {
            float4 u = *(const float4*)(xb + (size_t)jr * D_ + d0 + c4);
            float4 v = *(const float4*)(xb + (size_t)(jr + 1) * D_ + d0 + c4);
            dv = make_float4(v.x - u.x, v.y - u.y, v.z - u.z, v.w - u.w);
        }
        *(float4*)&sdiff[row][c4] = dv;
    }
    // coefficients (one thread per position); zero beyond cnt
    if (tid < TP) {
        int p = p0 + tid;
        int ws = p - IR; if (ws < 0) ws = 0;
        int cnt = p - ws;
        float wsz = (float)(cnt > 0 ? cnt : 1);
        float w[IR]; float sum = 0.f;
        #pragma unroll
        for (int t = 0; t < IR; ++t) w[t] = 0.f;
        for (int t = 0; t < cnt; ++t) {
            float wv = g_mw[b * (S_-1) + ws + t] * (float)(t + 1) / wsz;
            w[t] = wv; sum += wv;
        }
        float inv = 1.0f / fmaxf(sum, 1e-8f);
        #pragma unroll
        for (int t = 0; t < IR; ++t)
            scoef[tid][t] = (t < cnt) ? w[t] * inv * g_im[b * (S_-1) + ws + t] : 0.f;
    }
    __syncthreads();

    for (int i = tid; i < TP * (TDW / 4); i += 256) {
        int pi = i / (TDW / 4);
        int c4 = (i % (TDW / 4)) * 4;
        int p = p0 + pi;
        int ws = p - IR; if (ws < 0) ws = 0;
        int r0 = ws - base;                // 8..15
        float4 a = make_float4(0.f, 0.f, 0.f, 0.f);
        #pragma unroll
        for (int t = 0; t < IR; ++t) {
            float cf = scoef[pi][t];
            const float* dr = &sdiff[r0 + t][c4];
            a.x += cf * dr[0]; a.y += cf * dr[1];
            a.z += cf * dr[2]; a.w += cf * dr[3];
        }
        *(float4*)(traj + ((size_t)b * S_ + p) * D_ + d0 + c4) = a;
    }
}

// ======================================================================
// Splat weights -> bf16 hi/lo directly (packed f32x2 math, fused q+k)
// ======================================================================
__global__ __launch_bounds__(256)
void splat_weights_kernel(const float* __restrict__ centers,
                          const float* __restrict__ lsc,
                          const float* __restrict__ amp)
{
    int z = blockIdx.z;
    int which = z & 1;
    int b = z >> 1;
    int h = blockIdx.y;
    int s0 = blockIdx.x * 128;
    int tid = threadIdx.x;
    int off = which ? D_ : 0;

    __shared__ __align__(16) float cs[KS][HD];
    __shared__ float cn[KS], fac[KS], am[KS];
    __shared__ __align__(16) float ts[128][HD];
    __shared__ float tn[128];

    #pragma unroll
    for (int it = 0; it < 4; ++it) {
        int idx = tid + it * 256;
        int kk = idx >> 6, d = idx & 63;
        cs[kk][d] = centers[((size_t)h * KS + kk) * HD + d];
    }
    if (tid < KS) {
        float ls = lsc[h * KS + tid];
        fac[tid] = -0.5f * __expf(-2.0f * ls);
        float a  = amp[h * KS + tid];
        am[tid]  = 1.0f / (1.0f + __expf(-a));
    }
    const float* bse = g_qkv + ((size_t)b * S_ + s0) * TD + off + h * HD;
    #pragma unroll
    for (int it = 0; it < 8; ++it) {
        int idx = tid + it * 256;
        int s = idx >> 4, c4 = (idx & 15) * 4;
        *(float4*)&ts[s][c4] = *(const float4*)(bse + (size_t)s * TD + c4);
    }
    __syncthreads();
    if (tid < KS) {
        float s = 0.f;
        #pragma unroll
        for (int d = 0; d < HD; ++d) { float c = cs[tid][d]; s += c * c; }
        cn[tid] = s;
    }
    if (tid < 128) {
        const u64* tp = (const u64*)&ts[tid][0];
        u64 acc = 0ull;
        #pragma unroll
        for (int d = 0; d < 32; ++d) acc = ffma2(tp[d], tp[d], acc);
        float2 u = up2(acc);
        tn[tid] = u.x + u.y;
    }
    __syncthreads();

    #pragma unroll
    for (int it = 0; it < 8; ++it) {
        int idx = tid + it * 256;
        int s = idx >> 4, kk = idx & 15;
        const u64* tp = (const u64*)&ts[s][0];
        const u64* cp = (const u64*)&cs[kk][0];
        u64 acc = 0ull;
        #pragma unroll
        for (int d = 0; d < 32; ++d) acc = ffma2(tp[d], cp[d], acc);
        float2 u = up2(acc);
        float cross = u.x + u.y;
        float dist = tn[s] - 2.0f * cross + cn[kk];
        float w = __expf(fac[kk] * dist) * am[kk];
        __nv_bfloat16 hh = __float2bfloat16(w);
        float hf = __bfloat162float(hh);
        __nv_bfloat16 hl = __float2bfloat16(w - hf);
        size_t o = (((size_t)b * H_ + h) * S_ + s0 + s) * KS + kk;
        if (which) { g_kwh[o] = hh; g_kwl[o] = hl; }
        else       { g_qwh[o] = hh; g_qwl[o] = hl; }
    }
}

// ======================================================================
// HMMA flash attention. CTA = 64 queries of one (b,h); 4 warps x 16 q.
// (R9-proven configuration — 8-warp variant measured much slower.)
// ======================================================================
__global__ __launch_bounds__(128, 1)
void attn_mma_kernel()
{
    const int b = blockIdx.z, h = blockIdx.y;
    const int tid = threadIdx.x, lane = tid & 31, warp = tid >> 5;
    const int q0 = blockIdx.x * 64 + warp * 16;

    __shared__ __align__(16) __nv_bfloat16 skh[64][24];
    __shared__ __align__(16) __nv_bfloat16 skl[64][24];
    __shared__ __align__(16) __nv_bfloat16 svh[64][72];
    __shared__ __align__(16) __nv_bfloat16 svl[64][72];

    const int r4 = lane >> 2;
    const int c2 = (lane & 3) * 2;

    uint32_t qh[4], ql[4];
    {
        const __nv_bfloat16* qhb = g_qwh + (((size_t)b * H_ + h) * S_ + q0) * KS;
        const __nv_bfloat16* qlb = g_qwl + (((size_t)b * H_ + h) * S_ + q0) * KS;
        qh[0] = *(const uint32_t*)(qhb + (size_t)r4 * KS + c2);
        qh[1] = *(const uint32_t*)(qhb + (size_t)(r4 + 8) * KS + c2);
        qh[2] = *(const uint32_t*)(qhb + (size_t)r4 * KS + c2 + 8);
        qh[3] = *(const uint32_t*)(qhb + (size_t)(r4 + 8) * KS + c2 + 8);
        ql[0] = *(const uint32_t*)(qlb + (size_t)r4 * KS + c2);
        ql[1] = *(const uint32_t*)(qlb + (size_t)(r4 + 8) * KS + c2);
        ql[2] = *(const uint32_t*)(qlb + (size_t)r4 * KS + c2 + 8);
        ql[3] = *(const uint32_t*)(qlb + (size_t)(r4 + 8) * KS + c2 + 8);
    }

    float acc[8][4];
    #pragma unroll
    for (int i = 0; i < 8; ++i)
        #pragma unroll
        for (int q = 0; q < 4; ++q) acc[i][q] = 0.f;
    float den0 = 0.f, den1 = 0.f;

    const int jj  = lane >> 3, rin = lane & 7;
    const int k_row = ((jj >> 1) << 3) + rin;
    const int k_col = (jj & 1) * 8;
    const int v_row = lane & 15;
    const int v_col = (lane >> 4) * 8;

    const size_t kw_base = (((size_t)b * H_ + h) * S_) * KS;
    const size_t v_base  = ((size_t)b * S_) * D_ + h * HD;

    for (int j0 = 0; j0 < S_; j0 += 64) {
        {
            int row = tid >> 1, part = tid & 1;
            size_t gk = kw_base + (size_t)(j0 + row) * KS + part * 8;
            *(uint4*)&skh[row][part * 8] = *(const uint4*)(g_kwh + gk);
            *(uint4*)&skl[row][part * 8] = *(const uint4*)(g_kwl + gk);
        }
        #pragma unroll
        for (int i = 0; i < 4; ++i) {
            int idx = tid + i * 128;
            int row = idx >> 3, seg = idx & 7;
            size_t gv = v_base + (size_t)(j0 + row) * D_ + seg * 8;
            *(uint4*)&svh[row][seg * 8] = *(const uint4*)(g_vh + gv);
            *(uint4*)&svl[row][seg * 8] = *(const uint4*)(g_vl + gv);
        }
        __syncthreads();

        #pragma unroll
        for (int jt = 0; jt < 4; ++jt) {
            uint32_t kh[4], kl[4];
            ldsm4(smem_u32(&skh[jt * 16 + k_row][k_col]), kh);
            ldsm4(smem_u32(&skl[jt * 16 + k_row][k_col]), kl);

            float cz0[4] = {0.f, 0.f, 0.f, 0.f};
            float cz1[4] = {0.f, 0.f, 0.f, 0.f};
            mma_bf16(cz0, qh, kh);
            mma_bf16(cz0, ql, kh);
            mma_bf16(cz0, qh, kl);
            mma_bf16(cz1, qh, kh + 2);
            mma_bf16(cz1, ql, kh + 2);
            mma_bf16(cz1, qh, kl + 2);

            float e00 = __expf(cz0[0]), e01 = __expf(cz0[1]);
            float e02 = __expf(cz0[2]), e03 = __expf(cz0[3]);
            float e10 = __expf(cz1[0]), e11 = __expf(cz1[1]);
            float e12 = __expf(cz1[2]), e13 = __expf(cz1[3]);
            den0 += e00 + e01 + e10 + e11;
            den1 += e02 + e03 + e12 + e13;

            uint32_t ph[4], pl[4];
            ph[0] = cvt2bf(e00, e01);
            ph[1] = cvt2bf(e02, e03);
            ph[2] = cvt2bf(e10, e11);
            ph[3] = cvt2bf(e12, e13);
            pl[0] = cvt2bf(e00 - bflo(ph[0]), e01 - bfhi(ph[0]));
            pl[1] = cvt2bf(e02 - bflo(ph[1]), e03 - bfhi(ph[1]));
            pl[2] = cvt2bf(e10 - bflo(ph[2]), e11 - bfhi(ph[2]));
            pl[3] = cvt2bf(e12 - bflo(ph[3]), e13 - bfhi(ph[3]));

            #pragma unroll
            for (int dp = 0; dp < 4; ++dp) {
                uint32_t vh[4], vl[4];
                ldsm4t(smem_u32(&svh[jt * 16 + v_row][dp * 16 + v_col]), vh);
                ldsm4t(smem_u32(&svl[jt * 16 + v_row][dp * 16 + v_col]), vl);
                mma_bf16(acc[dp * 2],     ph, vh);
                mma_bf16(acc[dp * 2],     pl, vh);
                mma_bf16(acc[dp * 2],     ph, vl);
                mma_bf16(acc[dp * 2 + 1], ph, vh + 2);
                mma_bf16(acc[dp * 2 + 1], pl, vh + 2);
                mma_bf16(acc[dp * 2 + 1], ph, vl + 2);
            }
        }
        __syncthreads();
    }

    den0 += __shfl_xor_sync(0xffffffffu, den0, 1);
    den0 += __shfl_xor_sync(0xffffffffu, den0, 2);
    den1 += __shfl_xor_sync(0xffffffffu, den1, 1);
    den1 += __shfl_xor_sync(0xffffffffu, den1, 2);
    float inv0 = 1.0f / den0;
    float inv1 = 1.0f / den1;

    size_t row_a = ((size_t)b * S_ + q0 + r4) * D_ + h * HD;
    size_t row_b = ((size_t)b * S_ + q0 + r4 + 8) * D_ + h * HD;
    #pragma unroll
    for (int db = 0; db < 8; ++db) {
        int dc = db * 8 + c2;
        float o0 = acc[db][0] * inv0, o1 = acc[db][1] * inv0;
        float o2 = acc[db][2] * inv1, o3 = acc[db][3] * inv1;
        uint32_t h01 = cvt2bf(o0, o1), h23 = cvt2bf(o2, o3);
        uint32_t l01 = cvt2bf(o0 - bflo(h01), o1 - bfhi(h01));
        uint32_t l23 = cvt2bf(o2 - bflo(h23), o3 - bfhi(h23));
        *(uint32_t*)(g_aoh + row_a + dc) = h01;
        *(uint32_t*)(g_aoh + row_b + dc) = h23;
        *(uint32_t*)(g_aol + row_a + dc) = l01;
        *(uint32_t*)(g_aol + row_b + dc) = l23;
    }
}

// ======================================================================
// launch
// ======================================================================
extern "C" void kernel_launch(void* const* d_in, const int* in_sizes, int n_in,
                              void* d_out, int out_size)
{
    const float* x       = (const float*)d_in[0];
    const float* qkv_w   = (const float*)d_in[1];
    const float* out_w   = (const float*)d_in[2];
    const float* centers = (const float*)d_in[3];
    const float* lsc     = (const float*)d_in[4];
    const float* amps    = (const float*)d_in[5];
    float* out = (float*)d_out;

    const int BSD = B_ * S_ * D_;

    // ---- all input splits in one launch ----
    split_all_kernel<<<(NX4 + NW4 + NO4 + 255) / 256, 256>>>(x, qkv_w, out_w);

    // ---- trajectories -> second half of d_out ----
    {
        int warps = B_ * (S_ - 1);
        int blocks = (warps * 32 + 127) / 128;
        traj_mag_kernel<<<blocks, 128>>>(x);
        if (out_size >= 2 * BSD) {
            traj_out_kernel<<<dim3(S_ / TP, D_ / TDW, B_), 256>>>(x, out + BSD);
        }
    }

    // ---- qkv projection (V tiles written as bf16 hi/lo directly) ----
    hmma_qkv_kernel<<<dim3(TD / 128, (B_ * S_) / 128), 256, SS_SMEM_BYTES>>>();

    // ---- splat weights (bf16 hi/lo) ----
    splat_weights_kernel<<<dim3(S_ / 128, H_, 2 * B_), 256>>>(centers, lsc, amps);

    // ---- HMMA flash attention (4 warps / 64 queries per CTA) ----
    attn_mma_kernel<<<dim3(S_ / 64, H_, B_), 128>>>();

    // ---- output projection ----
    hmma_out_kernel<<<dim3(D_ / 128, (B_ * S_) / 128), 256, SS_SMEM_BYTES>>>(out);
}

// round 17
// speedup vs baseline: 1.7342x; 1.0334x over previous
#include <cuda_runtime.h>
#include <cuda_bf16.h>
#include <math.h>
#include <stdint.h>

// ---------------- problem constants (fixed shapes) ----------------
#define B_  2
#define S_  2048
#define D_  1024
#define H_  16
#define KS  16      // splats per head
#define HD  64      // head dim
#define TD  (3*D_)  // qkv row width = 3072
#define IR  8       // influence radius
#define KDIM 1024   // GEMM K for both projections

typedef unsigned long long u64;

// ---------------- packed f32x2 helpers ----------------
__device__ __forceinline__ float2 up2(u64 v) {
    float2 r; asm("mov.b64 {%0, %1}, %2;" : "=f"(r.x), "=f"(r.y) : "l"(v)); return r;
}
__device__ __forceinline__ u64 ffma2(u64 a, u64 b, u64 c) {
    u64 d; asm("fma.rn.f32x2 %0, %1, %2, %3;" : "=l"(d) : "l"(a), "l"(b), "l"(c));
    return d;
}

// ---------------- warp MMA / async-copy helpers (sm_80 baseline PTX) ----
__device__ __forceinline__ uint32_t smem_u32(const void* p) {
    uint32_t a;
    asm("{ .reg .u64 t; cvta.to.shared.u64 t, %1; cvt.u32.u64 %0, t; }" : "=r"(a) : "l"(p));
    return a;
}
__device__ __forceinline__ void ldsm4(uint32_t addr, uint32_t* r) {
    asm volatile("ldmatrix.sync.aligned.m8n8.x4.shared.b16 {%0,%1,%2,%3}, [%4];"
                 : "=r"(r[0]), "=r"(r[1]), "=r"(r[2]), "=r"(r[3]) : "r"(addr));
}
__device__ __forceinline__ void ldsm4t(uint32_t addr, uint32_t* r) {
    asm volatile("ldmatrix.sync.aligned.m8n8.x4.trans.shared.b16 {%0,%1,%2,%3}, [%4];"
                 : "=r"(r[0]), "=r"(r[1]), "=r"(r[2]), "=r"(r[3]) : "r"(addr));
}
__device__ __forceinline__ void mma_bf16(float* c, const uint32_t* a, const uint32_t* b) {
    asm volatile("mma.sync.aligned.m16n8k16.row.col.f32.bf16.bf16.f32 "
                 "{%0,%1,%2,%3}, {%4,%5,%6,%7}, {%8,%9}, {%0,%1,%2,%3};"
                 : "+f"(c[0]), "+f"(c[1]), "+f"(c[2]), "+f"(c[3])
                 : "r"(a[0]), "r"(a[1]), "r"(a[2]), "r"(a[3]), "r"(b[0]), "r"(b[1]));
}
__device__ __forceinline__ void cp16(uint32_t dst, const void* src) {
    asm volatile("cp.async.cg.shared.global [%0], [%1], 16;" :: "r"(dst), "l"(src) : "memory");
}
__device__ __forceinline__ void cp_commit() {
    asm volatile("cp.async.commit_group;" ::: "memory");
}
template<int N> __device__ __forceinline__ void cp_wait() {
    asm volatile("cp.async.wait_group %0;" :: "n"(N) : "memory");
}
__device__ __forceinline__ uint32_t cvt2bf(float lo, float hi) {
    uint32_t r; asm("cvt.rn.bf16x2.f32 %0, %1, %2;" : "=r"(r) : "f"(hi), "f"(lo)); return r;
}
__device__ __forceinline__ float bflo(uint32_t p) { return __uint_as_float(p << 16); }
__device__ __forceinline__ float bfhi(uint32_t p) { return __uint_as_float(p & 0xffff0000u); }

// ---------------- scratch (device globals; no allocation allowed) ----------------
// NOTE: reference these ONLY from device code (host-shadow pitfall, R6/R7).
__device__ __align__(16) float g_qkv[(size_t)B_ * S_ * TD];
__device__ float g_mw [B_ * (S_-1)];
__device__ float g_im [B_ * (S_-1)];
__device__ __align__(16) __nv_bfloat16 g_xh [(size_t)B_ * S_ * D_];
__device__ __align__(16) __nv_bfloat16 g_xl [(size_t)B_ * S_ * D_];
__device__ __align__(16) __nv_bfloat16 g_wh [(size_t)TD * D_];
__device__ __align__(16) __nv_bfloat16 g_wl [(size_t)TD * D_];
__device__ __align__(16) __nv_bfloat16 g_aoh[(size_t)B_ * S_ * D_];
__device__ __align__(16) __nv_bfloat16 g_aol[(size_t)B_ * S_ * D_];
__device__ __align__(16) __nv_bfloat16 g_owh[(size_t)D_ * D_];
__device__ __align__(16) __nv_bfloat16 g_owl[(size_t)D_ * D_];
__device__ __align__(16) __nv_bfloat16 g_qwh[(size_t)B_ * H_ * S_ * KS];
__device__ __align__(16) __nv_bfloat16 g_qwl[(size_t)B_ * H_ * S_ * KS];
__device__ __align__(16) __nv_bfloat16 g_kwh[(size_t)B_ * H_ * S_ * KS];
__device__ __align__(16) __nv_bfloat16 g_kwl[(size_t)B_ * H_ * S_ * KS];
__device__ __align__(16) __nv_bfloat16 g_vh [(size_t)B_ * S_ * D_];
__device__ __align__(16) __nv_bfloat16 g_vl [(size_t)B_ * S_ * D_];

// ======================================================================
// fp32 -> (hi, lo) bf16 split — all three inputs in ONE launch
// ======================================================================
#define NX4 ((B_ * S_ * D_) / 4)
#define NW4 ((TD * D_) / 4)
#define NO4 ((D_ * D_) / 4)

__device__ __forceinline__ void split_one(const float* __restrict__ in,
                                          __nv_bfloat16* __restrict__ hi,
                                          __nv_bfloat16* __restrict__ lo, int i)
{
    float4 v = ((const float4*)in)[i];
    float f[4] = {v.x, v.y, v.z, v.w};
    unsigned short hb[4], lb[4];
    #pragma unroll
    for (int j = 0; j < 4; ++j) {
        __nv_bfloat16 h = __float2bfloat16(f[j]);
        float hf = __bfloat162float(h);
        __nv_bfloat16 l = __float2bfloat16(f[j] - hf);
        hb[j] = __bfloat16_as_ushort(h);
        lb[j] = __bfloat16_as_ushort(l);
    }
    ((ushort4*)hi)[i] = make_ushort4(hb[0], hb[1], hb[2], hb[3]);
    ((ushort4*)lo)[i] = make_ushort4(lb[0], lb[1], lb[2], lb[3]);
}

__global__ __launch_bounds__(256)
void split_all_kernel(const float* __restrict__ x,
                      const float* __restrict__ w,
                      const float* __restrict__ ow)
{
    int gi = blockIdx.x * 256 + threadIdx.x;
    if (gi < NX4) {
        split_one(x, g_xh, g_xl, gi);
    } else if (gi < NX4 + NW4) {
        split_one(w, g_wh, g_wl, gi - NX4);
    } else {
        split_one(ow, g_owh, g_owl, gi - NX4 - NW4);
    }
}

// ======================================================================
// HMMA split-bf16 GEMM: C[M,N] = A[M,K]*B[N,K]^T, fp32 out.
// DB=true: cp.async 2-stage (80KB/CTA) + launch_bounds(256,2) -> 2 CTAs/SM
//          with WITHIN-CTA load/compute overlap (fixes the phase-lock that
//          capped tensor at 49%).
// DB=false: R15 single-stage fallback (40KB, no opt-in needed).
// WV=true (QKV gemm): tiles with n0>=2D are V -> bf16 hi/lo direct.
// ======================================================================
#define RSB   80
#define ARR_B (128 * RSB)
#define STG_B (4 * ARR_B)           // 40960 B per stage
#define SS_SMEM_BYTES STG_B
#define DB_SMEM_BYTES (2 * STG_B)   // 81920 B

template<bool DB, bool WV>
__device__ __forceinline__ void hmma_gemm_body(
    const __nv_bfloat16* __restrict__ Ah, const __nv_bfloat16* __restrict__ Al,
    const __nv_bfloat16* __restrict__ Bh, const __nv_bfloat16* __restrict__ Bl,
    float* __restrict__ C, int N)
{
    extern __shared__ char smem_raw[];
    const uint32_t base = smem_u32(smem_raw);

    const int tid  = threadIdx.x;
    const int lane = tid & 31;
    const int warp = tid >> 5;
    const int wm = warp >> 2;
    const int wn = warp & 3;
    const int m0 = blockIdx.y * 128;
    const int n0 = blockIdx.x * 128;

    const int j   = lane >> 3;
    const int rin = lane & 7;
    const uint32_t a_row = wm * 64 + ((j & 1) << 3) + rin;
    const uint32_t a_kb  = (j >> 1) << 4;
    const uint32_t b_row = wn * 32 + ((j >> 1) << 3) + rin;
    const uint32_t b_kb  = (j & 1) << 4;

    const int g_row0 = tid >> 2;
    const int g_cg   = tid & 3;

    float acc[4][4][4];
    #pragma unroll
    for (int mi = 0; mi < 4; ++mi)
        #pragma unroll
        for (int ni = 0; ni < 4; ++ni)
            #pragma unroll
            for (int q = 0; q < 4; ++q) acc[mi][ni][q] = 0.f;

    const __nv_bfloat16* srcs[4] = { Ah, Al, Bh, Bl };
    const int CH = KDIM / 32;

    auto compute = [&](uint32_t sb) {
        #pragma unroll
        for (int ks = 0; ks < 2; ++ks) {
            const uint32_t kbo = ks * 32;
            uint32_t ah[4][4], al[4][4], bh[4][2], bl[4][2];
            #pragma unroll
            for (int mi = 0; mi < 4; ++mi) {
                uint32_t addr = sb + (a_row + mi * 16) * RSB + kbo + a_kb;
                ldsm4(addr, ah[mi]);
                ldsm4(addr + ARR_B, al[mi]);
            }
            #pragma unroll
            for (int p = 0; p < 2; ++p) {
                uint32_t addr = sb + 2 * ARR_B + (b_row + p * 16) * RSB + kbo + b_kb;
                uint32_t rh[4], rl[4];
                ldsm4(addr, rh);
                ldsm4(addr + ARR_B, rl);
                bh[p*2+0][0] = rh[0]; bh[p*2+0][1] = rh[1];
                bh[p*2+1][0] = rh[2]; bh[p*2+1][1] = rh[3];
                bl[p*2+0][0] = rl[0]; bl[p*2+0][1] = rl[1];
                bl[p*2+1][0] = rl[2]; bl[p*2+1][1] = rl[3];
            }
            #pragma unroll
            for (int mi = 0; mi < 4; ++mi)
                #pragma unroll
                for (int ni = 0; ni < 4; ++ni) {
                    mma_bf16(acc[mi][ni], ah[mi], bh[ni]);
                    mma_bf16(acc[mi][ni], al[mi], bh[ni]);
                    mma_bf16(acc[mi][ni], ah[mi], bl[ni]);
                }
        }
    };

    if (DB) {
        auto issue = [&](int c, uint32_t sb) {
            #pragma unroll
            for (int arr = 0; arr < 4; ++arr) {
                const __nv_bfloat16* src = srcs[arr];
                const int rbase = (arr < 2) ? m0 : n0;
                #pragma unroll
                for (int i = 0; i < 2; ++i) {
                    int row = g_row0 + i * 64;
                    cp16(sb + arr * ARR_B + row * RSB + g_cg * 16,
                         src + (size_t)(rbase + row) * KDIM + c * 32 + g_cg * 8);
                }
            }
        };
        issue(0, base);
        cp_commit();
        for (int c = 0; c < CH; ++c) {
            const bool more = (c + 1 < CH);
            if (more) { issue(c + 1, base + ((c + 1) & 1) * STG_B); cp_commit(); }
            if (more) cp_wait<1>(); else cp_wait<0>();
            __syncthreads();
            compute(base + (c & 1) * STG_B);
            __syncthreads();     // buffer safe to overwrite by next issue
        }
    } else {
        for (int c = 0; c < CH; ++c) {
            if (c) __syncthreads();
            #pragma unroll
            for (int arr = 0; arr < 4; ++arr) {
                const __nv_bfloat16* src = srcs[arr];
                const int rbase = (arr < 2) ? m0 : n0;
                #pragma unroll
                for (int i = 0; i < 2; ++i) {
                    int row = g_row0 + i * 64;
                    uint4 v = *(const uint4*)(src + (size_t)(rbase + row) * KDIM + c * 32 + g_cg * 8);
                    uint32_t sa = base + arr * ARR_B + row * RSB + g_cg * 16;
                    asm volatile("st.shared.v4.b32 [%0], {%1,%2,%3,%4};"
                                 :: "r"(sa), "r"(v.x), "r"(v.y), "r"(v.z), "r"(v.w) : "memory");
                }
            }
            __syncthreads();
            compute(base);
        }
    }

    const int qr = lane >> 2;
    const int qc = (lane & 3) * 2;
    if (WV && n0 >= 2 * D_) {
        // V tile: write bf16 hi/lo splits directly
        const int cb = n0 - 2 * D_;
        #pragma unroll
        for (int mi = 0; mi < 4; ++mi) {
            #pragma unroll
            for (int ni = 0; ni < 4; ++ni) {
                int r  = m0 + wm * 64 + mi * 16 + qr;
                int cc = cb + wn * 32 + ni * 8 + qc;
                float a0 = acc[mi][ni][0], a1 = acc[mi][ni][1];
                float a2 = acc[mi][ni][2], a3 = acc[mi][ni][3];
                uint32_t h01 = cvt2bf(a0, a1), h23 = cvt2bf(a2, a3);
                uint32_t l01 = cvt2bf(a0 - bflo(h01), a1 - bfhi(h01));
                uint32_t l23 = cvt2bf(a2 - bflo(h23), a3 - bfhi(h23));
                *(uint32_t*)(g_vh + (size_t)r * D_ + cc)       = h01;
                *(uint32_t*)(g_vh + (size_t)(r + 8) * D_ + cc) = h23;
                *(uint32_t*)(g_vl + (size_t)r * D_ + cc)       = l01;
                *(uint32_t*)(g_vl + (size_t)(r + 8) * D_ + cc) = l23;
            }
        }
    } else {
        #pragma unroll
        for (int mi = 0; mi < 4; ++mi) {
            #pragma unroll
            for (int ni = 0; ni < 4; ++ni) {
                int r  = m0 + wm * 64 + mi * 16 + qr;
                int cc = n0 + wn * 32 + ni * 8 + qc;
                *(float2*)(C + (size_t)r * N + cc)       = make_float2(acc[mi][ni][0], acc[mi][ni][1]);
                *(float2*)(C + (size_t)(r + 8) * N + cc) = make_float2(acc[mi][ni][2], acc[mi][ni][3]);
            }
        }
    }
}

__global__ __launch_bounds__(256, 2)
void hmma_qkv_db() { hmma_gemm_body<true,  true >(g_xh, g_xl, g_wh, g_wl, g_qkv, TD); }
__global__ __launch_bounds__(256, 2)
void hmma_qkv_ss() { hmma_gemm_body<false, true >(g_xh, g_xl, g_wh, g_wl, g_qkv, TD); }
__global__ __launch_bounds__(256, 2)
void hmma_out_db(float* __restrict__ out) { hmma_gemm_body<true,  false>(g_aoh, g_aol, g_owh, g_owl, out, D_); }
__global__ __launch_bounds__(256, 2)
void hmma_out_ss(float* __restrict__ out) { hmma_gemm_body<false, false>(g_aoh, g_aol, g_owh, g_owl, out, D_); }

// ======================================================================
// Trajectory kernels
// ======================================================================
__global__ void traj_mag_kernel(const float* __restrict__ x)
{
    int gw   = (blockIdx.x * blockDim.x + threadIdx.x) >> 5;
    int lane = threadIdx.x & 31;
    if (gw >= B_ * (S_ - 1)) return;
    int b = gw / (S_ - 1);
    int j = gw % (S_ - 1);
    const float* r0 = x + ((size_t)b * S_ + j) * D_;
    const float* r1 = r0 + D_;
    float ss = 0.f;
    #pragma unroll
    for (int it = 0; it < D_ / (32 * 4); ++it) {
        int d = lane * 4 + it * 128;
        float4 a = *(const float4*)(r0 + d);
        float4 c = *(const float4*)(r1 + d);
        float dx = c.x - a.x, dy = c.y - a.y, dz = c.z - a.z, dw = c.w - a.w;
        ss += dx*dx + dy*dy + dz*dz + dw*dw;
    }
    #pragma unroll
    for (int o = 16; o; o >>= 1) ss += __shfl_xor_sync(0xffffffffu, ss, o);
    if (lane == 0) {
        float mag = sqrtf(ss);
        g_im[b * (S_-1) + j] = 1.0f / fmaxf(mag, 1e-8f);
        g_mw[b * (S_-1) + j] = tanhf(mag);
    }
}

// Tiled traj_out: block = 16 positions x 256-d slice.
#define TP  16
#define TDW 256
__global__ __launch_bounds__(256)
void traj_out_kernel(const float* __restrict__ x, float* __restrict__ traj)
{
    const int p0 = blockIdx.x * TP;
    const int d0 = blockIdx.y * TDW;
    const int b  = blockIdx.z;
    const int tid = threadIdx.x;

    __shared__ __align__(16) float sdiff[TP + 7][TDW];
    __shared__ float scoef[TP][IR];

    const int base = p0 - IR;
    const float* xb = x + (size_t)b * S_ * D_;

    for (int i = tid; i < 23 * (TDW / 4); i += 256) {
        int row = i / (TDW / 4);
        int c4  = (i % (TDW / 4)) * 4;
        int jr  = base + row;
        float4 dv = make_float4(0.f, 0.f, 0.f, 0.f);
        if (jr >= 0 && jr < S_ - 1) {
            float4 u = *(const float4*)(xb + (size_t)jr * D_ + d0 + c4);
            float4 v = *(const float4*)(xb + (size_t)(jr + 1) * D_ + d0 + c4);
            dv = make_float4(v.x - u.x, v.y - u.y, v.z - u.z, v.w - u.w);
        }
        *(float4*)&sdiff[row][c4] = dv;
    }
    if (tid < TP) {
        int p = p0 + tid;
        int ws = p - IR; if (ws < 0) ws = 0;
        int cnt = p - ws;
        float wsz = (float)(cnt > 0 ? cnt : 1);
        float w[IR]; float sum = 0.f;
        #pragma unroll
        for (int t = 0; t < IR; ++t) w[t] = 0.f;
        for (int t = 0; t < cnt; ++t) {
            float wv = g_mw[b * (S_-1) + ws + t] * (float)(t + 1) / wsz;
            w[t] = wv; sum += wv;
        }
        float inv = 1.0f / fmaxf(sum, 1e-8f);
        #pragma unroll
        for (int t = 0; t < IR; ++t)
            scoef[tid][t] = (t < cnt) ? w[t] * inv * g_im[b * (S_-1) + ws + t] : 0.f;
    }
    __syncthreads();

    for (int i = tid; i < TP * (TDW / 4); i += 256) {
        int pi = i / (TDW / 4);
        int c4 = (i % (TDW / 4)) * 4;
        int p = p0 + pi;
        int ws = p - IR; if (ws < 0) ws = 0;
        int r0 = ws - base;
        float4 a = make_float4(0.f, 0.f, 0.f, 0.f);
        #pragma unroll
        for (int t = 0; t < IR; ++t) {
            float cf = scoef[pi][t];
            const float* dr = &sdiff[r0 + t][c4];
            a.x += cf * dr[0]; a.y += cf * dr[1];
            a.z += cf * dr[2]; a.w += cf * dr[3];
        }
        *(float4*)(traj + ((size_t)b * S_ + p) * D_ + d0 + c4) = a;
    }
}

// ======================================================================
// Splat weights -> bf16 hi/lo directly (packed f32x2 math, fused q+k)
// ======================================================================
__global__ __launch_bounds__(256)
void splat_weights_kernel(const float* __restrict__ centers,
                          const float* __restrict__ lsc,
                          const float* __restrict__ amp)
{
    int z = blockIdx.z;
    int which = z & 1;
    int b = z >> 1;
    int h = blockIdx.y;
    int s0 = blockIdx.x * 128;
    int tid = threadIdx.x;
    int off = which ? D_ : 0;

    __shared__ __align__(16) float cs[KS][HD];
    __shared__ float cn[KS], fac[KS], am[KS];
    __shared__ __align__(16) float ts[128][HD];
    __shared__ float tn[128];

    #pragma unroll
    for (int it = 0; it < 4; ++it) {
        int idx = tid + it * 256;
        int kk = idx >> 6, d = idx & 63;
        cs[kk][d] = centers[((size_t)h * KS + kk) * HD + d];
    }
    if (tid < KS) {
        float ls = lsc[h * KS + tid];
        fac[tid] = -0.5f * __expf(-2.0f * ls);
        float a  = amp[h * KS + tid];
        am[tid]  = 1.0f / (1.0f + __expf(-a));
    }
    const float* bse = g_qkv + ((size_t)b * S_ + s0) * TD + off + h * HD;
    #pragma unroll
    for (int it = 0; it < 8; ++it) {
        int idx = tid + it * 256;
        int s = idx >> 4, c4 = (idx & 15) * 4;
        *(float4*)&ts[s][c4] = *(const float4*)(bse + (size_t)s * TD + c4);
    }
    __syncthreads();
    if (tid < KS) {
        float s = 0.f;
        #pragma unroll
        for (int d = 0; d < HD; ++d) { float c = cs[tid][d]; s += c * c; }
        cn[tid] = s;
    }
    if (tid < 128) {
        const u64* tp = (const u64*)&ts[tid][0];
        u64 acc = 0ull;
        #pragma unroll
        for (int d = 0; d < 32; ++d) acc = ffma2(tp[d], tp[d], acc);
        float2 u = up2(acc);
        tn[tid] = u.x + u.y;
    }
    __syncthreads();

    #pragma unroll
    for (int it = 0; it < 8; ++it) {
        int idx = tid + it * 256;
        int s = idx >> 4, kk = idx & 15;
        const u64* tp = (const u64*)&ts[s][0];
        const u64* cp = (const u64*)&cs[kk][0];
        u64 acc = 0ull;
        #pragma unroll
        for (int d = 0; d < 32; ++d) acc = ffma2(tp[d], cp[d], acc);
        float2 u = up2(acc);
        float cross = u.x + u.y;
        float dist = tn[s] - 2.0f * cross + cn[kk];
        float w = __expf(fac[kk] * dist) * am[kk];
        __nv_bfloat16 hh = __float2bfloat16(w);
        float hf = __bfloat162float(hh);
        __nv_bfloat16 hl = __float2bfloat16(w - hf);
        size_t o = (((size_t)b * H_ + h) * S_ + s0 + s) * KS + kk;
        if (which) { g_kwh[o] = hh; g_kwl[o] = hl; }
        else       { g_qwh[o] = hh; g_qwl[o] = hl; }
    }
}

// ======================================================================
// HMMA flash attention. CTA = 64 queries of one (b,h); 4 warps x 16 q.
// ======================================================================
__global__ __launch_bounds__(128, 1)
void attn_mma_kernel()
{
    const int b = blockIdx.z, h = blockIdx.y;
    const int tid = threadIdx.x, lane = tid & 31, warp = tid >> 5;
    const int q0 = blockIdx.x * 64 + warp * 16;

    __shared__ __align__(16) __nv_bfloat16 skh[64][24];
    __shared__ __align__(16) __nv_bfloat16 skl[64][24];
    __shared__ __align__(16) __nv_bfloat16 svh[64][72];
    __shared__ __align__(16) __nv_bfloat16 svl[64][72];

    const int r4 = lane >> 2;
    const int c2 = (lane & 3) * 2;

    uint32_t qh[4], ql[4];
    {
        const __nv_bfloat16* qhb = g_qwh + (((size_t)b * H_ + h) * S_ + q0) * KS;
        const __nv_bfloat16* qlb = g_qwl + (((size_t)b * H_ + h) * S_ + q0) * KS;
        qh[0] = *(const uint32_t*)(qhb + (size_t)r4 * KS + c2);
        qh[1] = *(const uint32_t*)(qhb + (size_t)(r4 + 8) * KS + c2);
        qh[2] = *(const uint32_t*)(qhb + (size_t)r4 * KS + c2 + 8);
        qh[3] = *(const uint32_t*)(qhb + (size_t)(r4 + 8) * KS + c2 + 8);
        ql[0] = *(const uint32_t*)(qlb + (size_t)r4 * KS + c2);
        ql[1] = *(const uint32_t*)(qlb + (size_t)(r4 + 8) * KS + c2);
        ql[2] = *(const uint32_t*)(qlb + (size_t)r4 * KS + c2 + 8);
        ql[3] = *(const uint32_t*)(qlb + (size_t)(r4 + 8) * KS + c2 + 8);
    }

    float acc[8][4];
    #pragma unroll
    for (int i = 0; i < 8; ++i)
        #pragma unroll
        for (int q = 0; q < 4; ++q) acc[i][q] = 0.f;
    float den0 = 0.f, den1 = 0.f;

    const int jj  = lane >> 3, rin = lane & 7;
    const int k_row = ((jj >> 1) << 3) + rin;
    const int k_col = (jj & 1) * 8;
    const int v_row = lane & 15;
    const int v_col = (lane >> 4) * 8;

    const size_t kw_base = (((size_t)b * H_ + h) * S_) * KS;
    const size_t v_base  = ((size_t)b * S_) * D_ + h * HD;

    for (int j0 = 0; j0 < S_; j0 += 64) {
        {
            int row = tid >> 1, part = tid & 1;
            size_t gk = kw_base + (size_t)(j0 + row) * KS + part * 8;
            *(uint4*)&skh[row][part * 8] = *(const uint4*)(g_kwh + gk);
            *(uint4*)&skl[row][part * 8] = *(const uint4*)(g_kwl + gk);
        }
        #pragma unroll
        for (int i = 0; i < 4; ++i) {
            int idx = tid + i * 128;
            int row = idx >> 3, seg = idx & 7;
            size_t gv = v_base + (size_t)(j0 + row) * D_ + seg * 8;
            *(uint4*)&svh[row][seg * 8] = *(const uint4*)(g_vh + gv);
            *(uint4*)&svl[row][seg * 8] = *(const uint4*)(g_vl + gv);
        }
        __syncthreads();

        #pragma unroll
        for (int jt = 0; jt < 4; ++jt) {
            uint32_t kh[4], kl[4];
            ldsm4(smem_u32(&skh[jt * 16 + k_row][k_col]), kh);
            ldsm4(smem_u32(&skl[jt * 16 + k_row][k_col]), kl);

            float cz0[4] = {0.f, 0.f, 0.f, 0.f};
            float cz1[4] = {0.f, 0.f, 0.f, 0.f};
            mma_bf16(cz0, qh, kh);
            mma_bf16(cz0, ql, kh);
            mma_bf16(cz0, qh, kl);
            mma_bf16(cz1, qh, kh + 2);
            mma_bf16(cz1, ql, kh + 2);
            mma_bf16(cz1, qh, kl + 2);

            float e00 = __expf(cz0[0]), e01 = __expf(cz0[1]);
            float e02 = __expf(cz0[2]), e03 = __expf(cz0[3]);
            float e10 = __expf(cz1[0]), e11 = __expf(cz1[1]);
            float e12 = __expf(cz1[2]), e13 = __expf(cz1[3]);
            den0 += e00 + e01 + e10 + e11;
            den1 += e02 + e03 + e12 + e13;

            uint32_t ph[4], pl[4];
            ph[0] = cvt2bf(e00, e01);
            ph[1] = cvt2bf(e02, e03);
            ph[2] = cvt2bf(e10, e11);
            ph[3] = cvt2bf(e12, e13);
            pl[0] = cvt2bf(e00 - bflo(ph[0]), e01 - bfhi(ph[0]));
            pl[1] = cvt2bf(e02 - bflo(ph[1]), e03 - bfhi(ph[1]));
            pl[2] = cvt2bf(e10 - bflo(ph[2]), e11 - bfhi(ph[2]));
            pl[3] = cvt2bf(e12 - bflo(ph[3]), e13 - bfhi(ph[3]));

            #pragma unroll
            for (int dp = 0; dp < 4; ++dp) {
                uint32_t vh[4], vl[4];
                ldsm4t(smem_u32(&svh[jt * 16 + v_row][dp * 16 + v_col]), vh);
                ldsm4t(smem_u32(&svl[jt * 16 + v_row][dp * 16 + v_col]), vl);
                mma_bf16(acc[dp * 2],     ph, vh);
                mma_bf16(acc[dp * 2],     pl, vh);
                mma_bf16(acc[dp * 2],     ph, vl);
                mma_bf16(acc[dp * 2 + 1], ph, vh + 2);
                mma_bf16(acc[dp * 2 + 1], pl, vh + 2);
                mma_bf16(acc[dp * 2 + 1], ph, vl + 2);
            }
        }
        __syncthreads();
    }

    den0 += __shfl_xor_sync(0xffffffffu, den0, 1);
    den0 += __shfl_xor_sync(0xffffffffu, den0, 2);
    den1 += __shfl_xor_sync(0xffffffffu, den1, 1);
    den1 += __shfl_xor_sync(0xffffffffu, den1, 2);
    float inv0 = 1.0f / den0;
    float inv1 = 1.0f / den1;

    size_t row_a = ((size_t)b * S_ + q0 + r4) * D_ + h * HD;
    size_t row_b = ((size_t)b * S_ + q0 + r4 + 8) * D_ + h * HD;
    #pragma unroll
    for (int db = 0; db < 8; ++db) {
        int dc = db * 8 + c2;
        float o0 = acc[db][0] * inv0, o1 = acc[db][1] * inv0;
        float o2 = acc[db][2] * inv1, o3 = acc[db][3] * inv1;
        uint32_t h01 = cvt2bf(o0, o1), h23 = cvt2bf(o2, o3);
        uint32_t l01 = cvt2bf(o0 - bflo(h01), o1 - bfhi(h01));
        uint32_t l23 = cvt2bf(o2 - bflo(h23), o3 - bfhi(h23));
        *(uint32_t*)(g_aoh + row_a + dc) = h01;
        *(uint32_t*)(g_aoh + row_b + dc) = h23;
        *(uint32_t*)(g_aol + row_a + dc) = l01;
        *(uint32_t*)(g_aol + row_b + dc) = l23;
    }
}

// ======================================================================
// launch
// ======================================================================
extern "C" void kernel_launch(void* const* d_in, const int* in_sizes, int n_in,
                              void* d_out, int out_size)
{
    const float* x       = (const float*)d_in[0];
    const float* qkv_w   = (const float*)d_in[1];
    const float* out_w   = (const float*)d_in[2];
    const float* centers = (const float*)d_in[3];
    const float* lsc     = (const float*)d_in[4];
    const float* amps    = (const float*)d_in[5];
    float* out = (float*)d_out;

    const int BSD = B_ * S_ * D_;

    // opt into >48KB dynamic smem for DB GEMMs; fall back if refused.
    bool db_ok =
        (cudaFuncSetAttribute(hmma_qkv_db, cudaFuncAttributeMaxDynamicSharedMemorySize,
                              DB_SMEM_BYTES) == cudaSuccess) &&
        (cudaFuncSetAttribute(hmma_out_db, cudaFuncAttributeMaxDynamicSharedMemorySize,
                              DB_SMEM_BYTES) == cudaSuccess);

    // ---- all input splits in one launch ----
    split_all_kernel<<<(NX4 + NW4 + NO4 + 255) / 256, 256>>>(x, qkv_w, out_w);

    // ---- trajectories -> second half of d_out ----
    {
        int warps = B_ * (S_ - 1);
        int blocks = (warps * 32 + 127) / 128;
        traj_mag_kernel<<<blocks, 128>>>(x);
        if (out_size >= 2 * BSD) {
            traj_out_kernel<<<dim3(S_ / TP, D_ / TDW, B_), 256>>>(x, out + BSD);
        }
    }

    // ---- qkv projection ----
    dim3 gq(TD / 128, (B_ * S_) / 128);
    if (db_ok) hmma_qkv_db<<<gq, 256, DB_SMEM_BYTES>>>();
    else       hmma_qkv_ss<<<gq, 256, SS_SMEM_BYTES>>>();

    // ---- splat weights (bf16 hi/lo) ----
    splat_weights_kernel<<<dim3(S_ / 128, H_, 2 * B_), 256>>>(centers, lsc, amps);

    // ---- HMMA flash attention (4 warps / 64 queries per CTA) ----
    attn_mma_kernel<<<dim3(S_ / 64, H_, B_), 128>>>();

    // ---- output projection ----
    dim3 go(D_ / 128, (B_ * S_) / 128);
    if (db_ok) hmma_out_db<<<go, 256, DB_SMEM_BYTES>>>(out);
    else       hmma_out_ss<<<go, 256, SS_SMEM_BYTES>>>(out);
}